// round 8
// baseline (speedup 1.0000x reference)
#include <cuda_runtime.h>
#include <cuda_bf16.h>
#include <cuda_fp16.h>
#include <math.h>

#define BTOT 262144
#define NBLK 2048

__device__ unsigned g_hh[(size_t)BTOT * 128];   // h bf16-hi pairs [B][128 pw]
__device__ unsigned g_hl[(size_t)BTOT * 128];   // h bf16-lo pairs
__device__ float    g_psum[256 * NBLK];
__device__ float    g_psq [256 * NBLK];
__device__ float    g_A[256], g_Bb[256], g_b2p[128];
__device__ unsigned short g_w1h[256 * 128], g_w1l[256 * 128];  // W1 [n][k] bf16
__device__ unsigned short g_w2h[128 * 256], g_w2l[128 * 256];  // W2' [n][k] bf16
__device__ unsigned g_we1p[5 * 128 * 64];   // We1 fp16 pairs [g][j 128][e-pw 64]
__device__ unsigned g_w2c [5 * 16 * 76];    // We2cat fp16 [g][a 16][k-pw 76]

__device__ __forceinline__ void mma16(float* c, const unsigned* a, const unsigned* b) {
    asm volatile("mma.sync.aligned.m16n8k16.row.col.f32.bf16.bf16.f32 "
        "{%0,%1,%2,%3},{%4,%5,%6,%7},{%8,%9},{%0,%1,%2,%3};"
        : "+f"(c[0]), "+f"(c[1]), "+f"(c[2]), "+f"(c[3])
        : "r"(a[0]), "r"(a[1]), "r"(a[2]), "r"(a[3]), "r"(b[0]), "r"(b[1]));
}
__device__ __forceinline__ void mma16h(float* c, const unsigned* a, const unsigned* b) {
    asm volatile("mma.sync.aligned.m16n8k16.row.col.f32.f16.f16.f32 "
        "{%0,%1,%2,%3},{%4,%5,%6,%7},{%8,%9},{%0,%1,%2,%3};"
        : "+f"(c[0]), "+f"(c[1]), "+f"(c[2]), "+f"(c[3])
        : "r"(a[0]), "r"(a[1]), "r"(a[2]), "r"(a[3]), "r"(b[0]), "r"(b[1]));
}
__device__ __forceinline__ unsigned short bh16(float v) {
    __nv_bfloat16 b = __float2bfloat16(v); return *(unsigned short*)&b;
}
__device__ __forceinline__ float bup(unsigned short u) {
    __nv_bfloat16 b = *(__nv_bfloat16*)&u; return __bfloat162float(b);
}
__device__ __forceinline__ void packpair(float v0, float v1, unsigned& hp, unsigned& lp) {
    unsigned short h0 = bh16(v0), h1 = bh16(v1);
    hp = (unsigned)h0 | ((unsigned)h1 << 16);
    lp = (unsigned)bh16(v0 - bup(h0)) | ((unsigned)bh16(v1 - bup(h1)) << 16);
}
__device__ __forceinline__ unsigned packh(float a, float b) {
    __half2 h = __floats2half2_rn(a, b); return *(unsigned*)&h;
}
__device__ __forceinline__ void cpa16(void* dst, const void* src) {
    unsigned d = (unsigned)__cvta_generic_to_shared(dst);
    asm volatile("cp.async.cg.shared.global [%0],[%1],16;\n" :: "r"(d), "l"(src));
}
#define CPCOMMIT asm volatile("cp.async.commit_group;\n")
#define CPWAIT0  asm volatile("cp.async.wait_group 0;\n")

// ------------------- prep -------------------
__global__ void k_prep(const float* __restrict__ W1, const float* __restrict__ We1,
                       const float* __restrict__ We2, const float* __restrict__ be2) {
    int idx = blockIdx.x * blockDim.x + threadIdx.x, st = gridDim.x * blockDim.x;
    for (int i = idx; i < 256 * 128; i += st) {
        int n = i >> 7, k = i & 127;
        float v = (k < 100) ? W1[k * 256 + n] : 0.f;
        unsigned short h = bh16(v);
        g_w1h[i] = h; g_w1l[i] = bh16(v - bup(h));
    }
    for (int i = idx; i < 5 * 128 * 64; i += st) {
        int g = i >> 13, r = i & 8191, j = r >> 6, ep = r & 63;
        int sub = j >> 6, jl = j & 63;
        float v0 = We1[((size_t)(2 * g + sub) * 128 + 2 * ep) * 64 + jl];
        float v1 = We1[((size_t)(2 * g + sub) * 128 + 2 * ep + 1) * 64 + jl];
        g_we1p[i] = packh(v0, v1);
    }
    for (int i = idx; i < 5 * 16 * 76; i += st) {
        int g = i / 1216, r = i - g * 1216, a = r / 76, pw = r - a * 76;
        float v0 = 0.f, v1 = 0.f;
        if (a < 10) {
            if (pw < 64) {
                int j0 = 2 * pw, j1 = 2 * pw + 1;
                v0 = We2[(size_t)((2 * g + (j0 >> 6)) * 64 + (j0 & 63)) * 10 + a];
                v1 = We2[(size_t)((2 * g + (j1 >> 6)) * 64 + (j1 & 63)) * 10 + a];
            } else if (pw == 64) {
                v0 = be2[2 * g * 10 + a]; v1 = be2[(2 * g + 1) * 10 + a];
            }
        }
        g_w2c[i] = packh(v0, v1);
    }
}

// ------- K1: h = relu(state@W1+b1), bf16 3-term, h stored as pair images ----
__global__ __launch_bounds__(512)
void k_gemm1(const float* __restrict__ state, const float* __restrict__ b1) {
    extern __shared__ unsigned sm[];
    unsigned* Ahi = sm;              // [128][68]
    unsigned* Alo = sm + 8704;
    unsigned* Bhi = sm + 17408;      // [256][68]
    unsigned* Blo = sm + 34816;      // end 52224 words
    const int t = threadIdx.x, w = t >> 5, lane = t & 31;
    const int gid = lane >> 2, q = lane & 3;
    const int wm = w >> 2, wn = w & 3, rowb = wm * 32, colb = wn * 64;
    const size_t row0 = (size_t)blockIdx.x * 128;

    for (int i = t; i < 1024; i += 512) {
        int r = i >> 3, sl = i & 7, c0 = sl * 16;
        float vv[16];
#pragma unroll
        for (int u = 0; u < 4; u++) {
            int k = c0 + u * 4;
            float4 x = (k < 100) ? *(const float4*)(state + (row0 + r) * 100 + k)
                                 : make_float4(0.f, 0.f, 0.f, 0.f);
            vv[4 * u] = x.x; vv[4 * u + 1] = x.y; vv[4 * u + 2] = x.z; vv[4 * u + 3] = x.w;
        }
        unsigned H[8], L[8];
#pragma unroll
        for (int u = 0; u < 8; u++) packpair(vv[2 * u], vv[2 * u + 1], H[u], L[u]);
        *(uint4*)(Ahi + r * 68 + sl * 8)     = make_uint4(H[0], H[1], H[2], H[3]);
        *(uint4*)(Ahi + r * 68 + sl * 8 + 4) = make_uint4(H[4], H[5], H[6], H[7]);
        *(uint4*)(Alo + r * 68 + sl * 8)     = make_uint4(L[0], L[1], L[2], L[3]);
        *(uint4*)(Alo + r * 68 + sl * 8 + 4) = make_uint4(L[4], L[5], L[6], L[7]);
    }
    {
        const unsigned* w1hw = (const unsigned*)g_w1h;
        const unsigned* w1lw = (const unsigned*)g_w1l;
        for (int i = t; i < 4096; i += 512) {
            int n = i >> 4, c4 = i & 15;
            *(uint4*)(Bhi + n * 68 + c4 * 4) = *(const uint4*)(w1hw + n * 64 + c4 * 4);
            *(uint4*)(Blo + n * 68 + c4 * 4) = *(const uint4*)(w1lw + n * 64 + c4 * 4);
        }
    }
    __syncthreads();

    float acc[2][8][4];
#pragma unroll
    for (int m = 0; m < 2; m++)
#pragma unroll
        for (int na = 0; na < 8; na++)
#pragma unroll
            for (int j = 0; j < 4; j++) acc[m][na][j] = 0.f;
#pragma unroll
    for (int ks = 0; ks < 8; ks++) {
        unsigned ah[2][4], al[2][4];
#pragma unroll
        for (int m = 0; m < 2; m++) {
            int b = (rowb + 16 * m + gid) * 68 + ks * 8 + q;
            ah[m][0] = Ahi[b]; ah[m][1] = Ahi[b + 544]; ah[m][2] = Ahi[b + 4]; ah[m][3] = Ahi[b + 548];
            al[m][0] = Alo[b]; al[m][1] = Alo[b + 544]; al[m][2] = Alo[b + 4]; al[m][3] = Alo[b + 548];
        }
#pragma unroll
        for (int na = 0; na < 8; na++) {
            int bb = (colb + 8 * na + gid) * 68 + ks * 8 + q;
            unsigned bh[2] = {Bhi[bb], Bhi[bb + 4]};
            unsigned bl[2] = {Blo[bb], Blo[bb + 4]};
#pragma unroll
            for (int m = 0; m < 2; m++) {
                mma16(acc[m][na], ah[m], bh);
                mma16(acc[m][na], al[m], bh);
                mma16(acc[m][na], ah[m], bl);
            }
        }
    }
    __syncthreads();
    float* sums = (float*)sm;     // [4][256]
    float* sqs  = sums + 1024;
#pragma unroll
    for (int na = 0; na < 8; na++) {
        int cg = colb + 8 * na + 2 * q, cg2 = cg >> 1;
        float bias0 = b1[cg], bias1 = b1[cg + 1];
        float p0 = 0.f, p1 = 0.f, q0 = 0.f, q1 = 0.f;
#pragma unroll
        for (int m = 0; m < 2; m++) {
            size_t r = row0 + rowb + 16 * m + gid;
            float v00 = fmaxf(acc[m][na][0] + bias0, 0.f), v01 = fmaxf(acc[m][na][1] + bias1, 0.f);
            float v10 = fmaxf(acc[m][na][2] + bias0, 0.f), v11 = fmaxf(acc[m][na][3] + bias1, 0.f);
            unsigned hp, lp;
            packpair(v00, v01, hp, lp);
            g_hh[r * 128 + cg2] = hp; g_hl[r * 128 + cg2] = lp;
            packpair(v10, v11, hp, lp);
            g_hh[(r + 8) * 128 + cg2] = hp; g_hl[(r + 8) * 128 + cg2] = lp;
            p0 += v00 + v10; p1 += v01 + v11;
            q0 += v00 * v00 + v10 * v10; q1 += v01 * v01 + v11 * v11;
        }
#pragma unroll
        for (int off = 4; off <= 16; off <<= 1) {
            p0 += __shfl_xor_sync(0xffffffffu, p0, off);
            p1 += __shfl_xor_sync(0xffffffffu, p1, off);
            q0 += __shfl_xor_sync(0xffffffffu, q0, off);
            q1 += __shfl_xor_sync(0xffffffffu, q1, off);
        }
        if (gid == 0) {
            sums[wm * 256 + cg] = p0; sums[wm * 256 + cg + 1] = p1;
            sqs [wm * 256 + cg] = q0; sqs [wm * 256 + cg + 1] = q1;
        }
    }
    __syncthreads();
    if (t < 256) {
        float S = sums[t] + sums[256 + t] + sums[512 + t] + sums[768 + t];
        float Q = sqs[t] + sqs[256 + t] + sqs[512 + t] + sqs[768 + t];
        g_psum[t * NBLK + blockIdx.x] = S;
        g_psq [t * NBLK + blockIdx.x] = Q;
    }
}

// ------------------- K2: BN stats finalize -------------------
__global__ __launch_bounds__(256)
void k_stats(const float* __restrict__ gamma, const float* __restrict__ beta) {
    const int c = blockIdx.x, t = threadIdx.x;
    float s = 0.f, qq = 0.f;
    for (int i = t; i < NBLK; i += 256) { s += g_psum[c * NBLK + i]; qq += g_psq[c * NBLK + i]; }
#pragma unroll
    for (int off = 16; off; off >>= 1) {
        s += __shfl_xor_sync(0xffffffffu, s, off);
        qq += __shfl_xor_sync(0xffffffffu, qq, off);
    }
    __shared__ float ss[8], sq[8];
    if ((t & 31) == 0) { ss[t >> 5] = s; sq[t >> 5] = qq; }
    __syncthreads();
    if (t == 0) {
        float S = 0.f, Q = 0.f;
#pragma unroll
        for (int wv = 0; wv < 8; wv++) { S += ss[wv]; Q += sq[wv]; }
        const float inv_n = 1.f / (float)BTOT;
        float mu = S * inv_n;
        float var = Q * inv_n - mu * mu;
        float rstd = rsqrtf(var + 1e-5f);
        float gg = gamma[c];
        g_A[c] = rstd * gg;
        g_Bb[c] = beta[c] - mu * rstd * gg;
    }
}

// ------------- K2b: fold BN into W2 (bf16 split) + b2' ---------------
__global__ __launch_bounds__(256)
void k_fold(const float* __restrict__ W2, const float* __restrict__ b2) {
    const int n = blockIdx.x, k = threadIdx.x;
    float sc = g_A[k] * W2[k * 128 + n];
    unsigned short h = bh16(sc);
    g_w2h[n * 256 + k] = h;
    g_w2l[n * 256 + k] = bh16(sc - bup(h));
    float p = g_Bb[k] * W2[k * 128 + n];
#pragma unroll
    for (int off = 16; off; off >>= 1) p += __shfl_xor_sync(0xffffffffu, p, off);
    __shared__ float red[8];
    if ((k & 31) == 0) red[k >> 5] = p;
    __syncthreads();
    if (k == 0) {
        float S = 0.f;
#pragma unroll
        for (int i = 0; i < 8; i++) S += red[i];
        g_b2p[n] = b2[n] + S;
    }
}

// -- K3: enc = tanh(h@W2'+b2') + softmax + experts + output, all fused ------
__global__ __launch_bounds__(512)
void k_gemm2f(const float* __restrict__ att, const float* __restrict__ be1,
              float* __restrict__ out) {
    extern __shared__ unsigned sm[];
    // phase 1
    unsigned* Ahi = sm;                   // [128][68]
    unsigned* Alo = sm + 8704;
    unsigned* Bhi = sm + 17408;           // [128][68]
    unsigned* Blo = sm + 26112;           // end 34816
    float* attS = (float*)(sm + 34816);   // [10][128]
    float* b2ps = (float*)(sm + 36096);   // [128]
    // phase 2 aliases (dead-after-MMA regions)
    float*    encS = (float*)sm;          // [128][132] fp32
    unsigned* encH = sm + 16896;          // [128][68] fp16 pairs
    unsigned* buf  = sm + 25600;          // [128][76] We1 / eh
    unsigned* B2   = sm + 35328;          // [16][76]
    float* sS  = (float*)(sm + 36544);    // [128][12]
    float* sBe = (float*)(sm + 38080);    // [128]; total 38208 words
    const int t = threadIdx.x, w = t >> 5, lane = t & 31;
    const int gid = lane >> 2, q = lane & 3;
    const int wm = w >> 2, wn = w & 3, rowb = wm * 32, colb = wn * 32;
    const size_t row0 = (size_t)blockIdx.x * 128;

    for (int i = t; i < 1280; i += 512) attS[i] = att[i];
    if (t < 128) b2ps[t] = g_b2p[t];

    float acc[2][4][4];
#pragma unroll
    for (int m = 0; m < 2; m++)
#pragma unroll
        for (int na = 0; na < 4; na++)
#pragma unroll
            for (int j = 0; j < 4; j++) acc[m][na][j] = 0.f;

    const unsigned* w2hw = (const unsigned*)g_w2h;
    const unsigned* w2lw = (const unsigned*)g_w2l;
    for (int kc = 0; kc < 2; kc++) {
        __syncthreads();
        for (int i = t; i < 2048; i += 512) {
            int r = i >> 4, c4 = i & 15;
            cpa16(Ahi + r * 68 + c4 * 4, g_hh + (row0 + r) * 128 + kc * 64 + c4 * 4);
            cpa16(Alo + r * 68 + c4 * 4, g_hl + (row0 + r) * 128 + kc * 64 + c4 * 4);
        }
        CPCOMMIT;
        for (int i = t; i < 2048; i += 512) {
            int n = i >> 4, c4 = i & 15;
            *(uint4*)(Bhi + n * 68 + c4 * 4) = *(const uint4*)(w2hw + n * 128 + kc * 64 + c4 * 4);
            *(uint4*)(Blo + n * 68 + c4 * 4) = *(const uint4*)(w2lw + n * 128 + kc * 64 + c4 * 4);
        }
        CPWAIT0;
        __syncthreads();
#pragma unroll
        for (int ks = 0; ks < 8; ks++) {
            unsigned ah[2][4], al[2][4];
#pragma unroll
            for (int m = 0; m < 2; m++) {
                int b = (rowb + 16 * m + gid) * 68 + ks * 8 + q;
                ah[m][0] = Ahi[b]; ah[m][1] = Ahi[b + 544]; ah[m][2] = Ahi[b + 4]; ah[m][3] = Ahi[b + 548];
                al[m][0] = Alo[b]; al[m][1] = Alo[b + 544]; al[m][2] = Alo[b + 4]; al[m][3] = Alo[b + 548];
            }
#pragma unroll
            for (int na = 0; na < 4; na++) {
                int bb = (colb + 8 * na + gid) * 68 + ks * 8 + q;
                unsigned bh[2] = {Bhi[bb], Bhi[bb + 4]};
                unsigned bl[2] = {Blo[bb], Blo[bb + 4]};
#pragma unroll
                for (int m = 0; m < 2; m++) {
                    mma16(acc[m][na], ah[m], bh);
                    mma16(acc[m][na], al[m], bh);
                    mma16(acc[m][na], ah[m], bl);
                }
            }
        }
    }
    __syncthreads();
    // epilogue: tanh -> encS (fp32) + encH (fp16 pairs)
#pragma unroll
    for (int na = 0; na < 4; na++) {
        int cl = colb + 8 * na + 2 * q;
        float bb0 = b2ps[cl], bb1 = b2ps[cl + 1];
#pragma unroll
        for (int m = 0; m < 2; m++) {
            int r = rowb + 16 * m + gid;
            float e00 = tanhf(acc[m][na][0] + bb0), e01 = tanhf(acc[m][na][1] + bb1);
            float e10 = tanhf(acc[m][na][2] + bb0), e11 = tanhf(acc[m][na][3] + bb1);
            encS[r * 132 + cl] = e00;       encS[r * 132 + cl + 1] = e01;
            encS[(r + 8) * 132 + cl] = e10; encS[(r + 8) * 132 + cl + 1] = e11;
            encH[r * 68 + (cl >> 1)]       = packh(e00, e01);
            encH[(r + 8) * 68 + (cl >> 1)] = packh(e10, e11);
        }
    }
    __syncthreads();
    // distances + softmax -> sS (smem)
    for (int it = 0; it < 8; it++) {
        int r = w * 8 + it;
        float4 e4 = *(float4*)(encS + r * 132 + lane * 4);
        float d[10];
#pragma unroll
        for (int k = 0; k < 10; k++) {
            float4 aa = *(float4*)(attS + k * 128 + lane * 4);
            float dx = e4.x - aa.x, dy = e4.y - aa.y, dz = e4.z - aa.z, dw = e4.w - aa.w;
            float p = dx * dx + dy * dy + dz * dz + dw * dw;
#pragma unroll
            for (int off = 16; off; off >>= 1) p += __shfl_xor_sync(0xffffffffu, p, off);
            d[k] = sqrtf(p);
        }
        float dmin = d[0];
#pragma unroll
        for (int k = 1; k < 10; k++) dmin = fminf(dmin, d[k]);
        float s[10], Z = 0.f;
#pragma unroll
        for (int k = 0; k < 10; k++) { s[k] = expf(-2.f * (d[k] - dmin)); Z += s[k]; }
        float invZ = 1.f / Z;
#pragma unroll
        for (int k = 0; k < 10; k++)
            if (lane == k) sS[r * 12 + k] = s[k] * invZ;
    }

    // phase 2: experts (fp16 k16) + gated contraction
    float acc2[2][4];
#pragma unroll
    for (int nf = 0; nf < 2; nf++)
#pragma unroll
        for (int j = 0; j < 4; j++) acc2[nf][j] = 0.f;

    for (int g = 0; g < 5; g++) {
        __syncthreads();
        for (int i = t; i < 2048; i += 512) {
            int j = i >> 4, c4 = i & 15;
            cpa16(buf + j * 68 + c4 * 4, g_we1p + g * 8192 + j * 64 + c4 * 4);
        }
        CPCOMMIT;
        if (t < 128) sBe[t] = be1[g * 128 + t];
        for (int i = t; i < 304; i += 512)
            ((uint4*)B2)[i] = ((const uint4*)(g_w2c + g * 1216))[i];
        CPWAIT0;
        __syncthreads();

        float acce[2][4][4];
#pragma unroll
        for (int m = 0; m < 2; m++)
#pragma unroll
            for (int na = 0; na < 4; na++)
#pragma unroll
                for (int j = 0; j < 4; j++) acce[m][na][j] = 0.f;
#pragma unroll
        for (int ks = 0; ks < 8; ks++) {
            unsigned a[2][4];
#pragma unroll
            for (int m = 0; m < 2; m++) {
                int b = (wm * 32 + 16 * m + gid) * 68 + ks * 8 + q;
                a[m][0] = encH[b]; a[m][1] = encH[b + 544]; a[m][2] = encH[b + 4]; a[m][3] = encH[b + 548];
            }
#pragma unroll
            for (int na = 0; na < 4; na++) {
                int bb = (wn * 32 + 8 * na + gid) * 68 + ks * 8 + q;
                unsigned bh[2] = {buf[bb], buf[bb + 4]};
                mma16h(acce[0][na], a[0], bh);
                mma16h(acce[1][na], a[1], bh);
            }
        }
        __syncthreads();
#pragma unroll
        for (int na = 0; na < 4; na++) {
            int jc = wn * 32 + 8 * na + 2 * q, pw = wn * 16 + 4 * na + q;
            float bia0 = sBe[jc], bia1 = sBe[jc + 1];
            int k0 = 2 * g + (jc >> 6);
#pragma unroll
            for (int m = 0; m < 2; m++) {
                int rr = wm * 32 + 16 * m + gid;
                float s0 = sS[rr * 12 + k0], s1 = sS[(rr + 8) * 12 + k0];
                buf[rr * 76 + pw] = packh(fmaxf(acce[m][na][0] + bia0, 0.f) * s0,
                                          fmaxf(acce[m][na][1] + bia1, 0.f) * s0);
                buf[(rr + 8) * 76 + pw] = packh(fmaxf(acce[m][na][2] + bia0, 0.f) * s1,
                                                fmaxf(acce[m][na][3] + bia1, 0.f) * s1);
            }
        }
        for (int i = t; i < 1024; i += 512) {
            int r = i >> 3, pw = 64 + (i & 7);
            buf[r * 76 + pw] = (pw == 64) ? packh(sS[r * 12 + 2 * g], sS[r * 12 + 2 * g + 1]) : 0u;
        }
        __syncthreads();
        if (w < 8) {
#pragma unroll
            for (int ks = 0; ks < 9; ks++) {
                int b = (w * 16 + gid) * 76 + ks * 8 + q;
                unsigned a2[4] = {buf[b], buf[b + 608], buf[b + 4], buf[b + 612]};
#pragma unroll
                for (int nf = 0; nf < 2; nf++) {
                    int bb = (nf * 8 + gid) * 76 + ks * 8 + q;
                    unsigned bh[2] = {B2[bb], B2[bb + 4]};
                    mma16h(acc2[nf], a2, bh);
                }
            }
        }
    }
    if (w < 8) {
        size_t r = row0 + w * 16 + gid;
        out[r * 10 + 2 * q]           = acc2[0][0];
        out[r * 10 + 2 * q + 1]       = acc2[0][1];
        out[(r + 8) * 10 + 2 * q]     = acc2[0][2];
        out[(r + 8) * 10 + 2 * q + 1] = acc2[0][3];
        if (q == 0) {
            out[r * 10 + 8] = acc2[1][0];       out[r * 10 + 9] = acc2[1][1];
            out[(r + 8) * 10 + 8] = acc2[1][2]; out[(r + 8) * 10 + 9] = acc2[1][3];
        }
    }
}

// ---------------------------------------------------------------------------
extern "C" void kernel_launch(void* const* d_in, const int* in_sizes, int n_in,
                              void* d_out, int out_size) {
    const float* state = (const float*)d_in[0];
    const float* W1    = (const float*)d_in[1];
    const float* b1    = (const float*)d_in[2];
    const float* gamma = (const float*)d_in[3];
    const float* beta  = (const float*)d_in[4];
    const float* W2    = (const float*)d_in[5];
    const float* b2    = (const float*)d_in[6];
    const float* We1   = (const float*)d_in[7];
    const float* be1   = (const float*)d_in[8];
    const float* We2   = (const float*)d_in[9];
    const float* be2   = (const float*)d_in[10];
    const float* att   = (const float*)d_in[11];
    float* out = (float*)d_out;

    const int SM1 = 52224 * 4, SM2F = 38208 * 4;
    cudaFuncSetAttribute(k_gemm1,  cudaFuncAttributeMaxDynamicSharedMemorySize, SM1);
    cudaFuncSetAttribute(k_gemm2f, cudaFuncAttributeMaxDynamicSharedMemorySize, SM2F);

    k_prep  <<<256, 256>>>(W1, We1, We2, be2);
    k_gemm1 <<<NBLK, 512, SM1>>>(state, b1);
    k_stats <<<256, 256>>>(gamma, beta);
    k_fold  <<<128, 256>>>(W2, b2);
    k_gemm2f<<<NBLK, 512, SM2F>>>(att, be1, out);
}

// round 9
// speedup vs baseline: 1.1827x; 1.1827x over previous
#include <cuda_runtime.h>
#include <cuda_bf16.h>
#include <cuda_fp16.h>
#include <math.h>

#define BTOT 262144
#define NB1  4096   // gemm1/gemm2 row blocks (64 rows)
#define NBF  2048   // fused row blocks (128 rows)

__device__ unsigned g_hh[(size_t)BTOT * 128];   // h bf16-hi pairs
__device__ unsigned g_hl[(size_t)BTOT * 128];   // h bf16-lo pairs
__device__ unsigned g_ench[(size_t)BTOT * 64];  // enc fp16 pairs
__device__ float    g_s[(size_t)BTOT * 10];
__device__ float    g_psum[256 * NB1];
__device__ float    g_psq [256 * NB1];
__device__ float    g_A[256], g_Bb[256], g_b2p[128];
__device__ unsigned short g_w1h[256 * 128], g_w1l[256 * 128];  // W1 [n][k]
__device__ unsigned short g_w2h[128 * 256], g_w2l[128 * 256];  // W2' [n][k]
__device__ unsigned g_we1p[5 * 128 * 64];
__device__ unsigned g_w2c [5 * 16 * 76];

__device__ __forceinline__ void mma16(float* c, const unsigned* a, const unsigned* b) {
    asm volatile("mma.sync.aligned.m16n8k16.row.col.f32.bf16.bf16.f32 "
        "{%0,%1,%2,%3},{%4,%5,%6,%7},{%8,%9},{%0,%1,%2,%3};"
        : "+f"(c[0]), "+f"(c[1]), "+f"(c[2]), "+f"(c[3])
        : "r"(a[0]), "r"(a[1]), "r"(a[2]), "r"(a[3]), "r"(b[0]), "r"(b[1]));
}
__device__ __forceinline__ void mma16h(float* c, const unsigned* a, const unsigned* b) {
    asm volatile("mma.sync.aligned.m16n8k16.row.col.f32.f16.f16.f32 "
        "{%0,%1,%2,%3},{%4,%5,%6,%7},{%8,%9},{%0,%1,%2,%3};"
        : "+f"(c[0]), "+f"(c[1]), "+f"(c[2]), "+f"(c[3])
        : "r"(a[0]), "r"(a[1]), "r"(a[2]), "r"(a[3]), "r"(b[0]), "r"(b[1]));
}
__device__ __forceinline__ unsigned short bh16(float v) {
    __nv_bfloat16 b = __float2bfloat16(v); return *(unsigned short*)&b;
}
__device__ __forceinline__ float bup(unsigned short u) {
    __nv_bfloat16 b = *(__nv_bfloat16*)&u; return __bfloat162float(b);
}
__device__ __forceinline__ void packpair(float v0, float v1, unsigned& hp, unsigned& lp) {
    unsigned short h0 = bh16(v0), h1 = bh16(v1);
    hp = (unsigned)h0 | ((unsigned)h1 << 16);
    lp = (unsigned)bh16(v0 - bup(h0)) | ((unsigned)bh16(v1 - bup(h1)) << 16);
}
__device__ __forceinline__ unsigned packh(float a, float b) {
    __half2 h = __floats2half2_rn(a, b); return *(unsigned*)&h;
}
__device__ __forceinline__ void cpa16(void* dst, const void* src) {
    unsigned d = (unsigned)__cvta_generic_to_shared(dst);
    asm volatile("cp.async.cg.shared.global [%0],[%1],16;\n" :: "r"(d), "l"(src));
}
#define CPCOMMIT asm volatile("cp.async.commit_group;\n")
#define CPWAIT0  asm volatile("cp.async.wait_group 0;\n")

// ------------------- prep -------------------
__global__ void k_prep(const float* __restrict__ W1, const float* __restrict__ We1,
                       const float* __restrict__ We2, const float* __restrict__ be2) {
    int idx = blockIdx.x * blockDim.x + threadIdx.x, st = gridDim.x * blockDim.x;
    for (int i = idx; i < 256 * 128; i += st) {
        int n = i >> 7, k = i & 127;
        float v = (k < 100) ? W1[k * 256 + n] : 0.f;
        unsigned short h = bh16(v);
        g_w1h[i] = h; g_w1l[i] = bh16(v - bup(h));
    }
    for (int i = idx; i < 5 * 128 * 64; i += st) {
        int g = i >> 13, r = i & 8191, j = r >> 6, ep = r & 63;
        int sub = j >> 6, jl = j & 63;
        float v0 = We1[((size_t)(2 * g + sub) * 128 + 2 * ep) * 64 + jl];
        float v1 = We1[((size_t)(2 * g + sub) * 128 + 2 * ep + 1) * 64 + jl];
        g_we1p[i] = packh(v0, v1);
    }
    for (int i = idx; i < 5 * 16 * 76; i += st) {
        int g = i / 1216, r = i - g * 1216, a = r / 76, pw = r - a * 76;
        float v0 = 0.f, v1 = 0.f;
        if (a < 10) {
            if (pw < 64) {
                int j0 = 2 * pw, j1 = 2 * pw + 1;
                v0 = We2[(size_t)((2 * g + (j0 >> 6)) * 64 + (j0 & 63)) * 10 + a];
                v1 = We2[(size_t)((2 * g + (j1 >> 6)) * 64 + (j1 & 63)) * 10 + a];
            } else if (pw == 64) {
                v0 = be2[2 * g * 10 + a]; v1 = be2[(2 * g + 1) * 10 + a];
            }
        }
        g_w2c[i] = packh(v0, v1);
    }
}

// -- K1: h = relu(state@W1+b1), bf16 3-term. Tile 64x128, K-chunks of 64. ----
// grid (NB1, 2): rb = row block (64 rows), cb = col half (128 cols).
__global__ __launch_bounds__(256, 3)
void k_gemm1(const float* __restrict__ state, const float* __restrict__ b1) {
    extern __shared__ unsigned sm[];
    unsigned* Ahi = sm;            // [64][36]
    unsigned* Alo = sm + 2304;
    unsigned* Bhi = sm + 4608;     // [128][36]
    unsigned* Blo = sm + 9216;     // end 13824 words
    const int t = threadIdx.x, w = t >> 5, lane = t & 31;
    const int gid = lane >> 2, q = lane & 3;
    const int wm = w >> 2, wn = w & 3, rowb = wm * 32, colb = wn * 32;
    const int rb = blockIdx.x, cb = blockIdx.y;
    const size_t row0 = (size_t)rb * 64;
    const unsigned* w1hw = (const unsigned*)g_w1h;
    const unsigned* w1lw = (const unsigned*)g_w1l;

    float acc[2][4][4];
#pragma unroll
    for (int m = 0; m < 2; m++)
#pragma unroll
        for (int na = 0; na < 4; na++)
#pragma unroll
            for (int j = 0; j < 4; j++) acc[m][na][j] = 0.f;

    for (int kc = 0; kc < 2; kc++) {
        __syncthreads();
        {   // A pack: 64 rows x 64 k
            int r = t >> 2, sl = t & 3, c0 = kc * 64 + sl * 16;
            float vv[16];
#pragma unroll
            for (int u = 0; u < 4; u++) {
                int k = c0 + u * 4;
                float4 x = (k < 100) ? *(const float4*)(state + (row0 + r) * 100 + k)
                                     : make_float4(0.f, 0.f, 0.f, 0.f);
                vv[4 * u] = x.x; vv[4 * u + 1] = x.y; vv[4 * u + 2] = x.z; vv[4 * u + 3] = x.w;
            }
            unsigned H[8], L[8];
#pragma unroll
            for (int u = 0; u < 8; u++) packpair(vv[2 * u], vv[2 * u + 1], H[u], L[u]);
            *(uint4*)(Ahi + r * 36 + sl * 8)     = make_uint4(H[0], H[1], H[2], H[3]);
            *(uint4*)(Ahi + r * 36 + sl * 8 + 4) = make_uint4(H[4], H[5], H[6], H[7]);
            *(uint4*)(Alo + r * 36 + sl * 8)     = make_uint4(L[0], L[1], L[2], L[3]);
            *(uint4*)(Alo + r * 36 + sl * 8 + 4) = make_uint4(L[4], L[5], L[6], L[7]);
        }
        for (int i = t; i < 1024; i += 256) {
            int n = i >> 3, c8 = i & 7;
            size_t gi = (size_t)(cb * 128 + n) * 64 + kc * 32 + c8 * 4;
            *(uint4*)(Bhi + n * 36 + c8 * 4) = *(const uint4*)(w1hw + gi);
            *(uint4*)(Blo + n * 36 + c8 * 4) = *(const uint4*)(w1lw + gi);
        }
        __syncthreads();
#pragma unroll
        for (int ks = 0; ks < 4; ks++) {
            unsigned ah[2][4], al[2][4];
#pragma unroll
            for (int m = 0; m < 2; m++) {
                int b = (rowb + 16 * m + gid) * 36 + ks * 8 + q;
                ah[m][0] = Ahi[b]; ah[m][1] = Ahi[b + 288]; ah[m][2] = Ahi[b + 4]; ah[m][3] = Ahi[b + 292];
                al[m][0] = Alo[b]; al[m][1] = Alo[b + 288]; al[m][2] = Alo[b + 4]; al[m][3] = Alo[b + 292];
            }
#pragma unroll
            for (int na = 0; na < 4; na++) {
                int bb = (colb + 8 * na + gid) * 36 + ks * 8 + q;
                unsigned bh[2] = {Bhi[bb], Bhi[bb + 4]};
                unsigned bl[2] = {Blo[bb], Blo[bb + 4]};
#pragma unroll
                for (int m = 0; m < 2; m++) {
                    mma16(acc[m][na], ah[m], bh);
                    mma16(acc[m][na], al[m], bh);
                    mma16(acc[m][na], ah[m], bl);
                }
            }
        }
    }
    __syncthreads();
    float* sums = (float*)sm;     // [2][128]
    float* sqs  = sums + 256;
#pragma unroll
    for (int na = 0; na < 4; na++) {
        int cg = colb + 8 * na + 2 * q, cgg = cb * 128 + cg;
        float bias0 = b1[cgg], bias1 = b1[cgg + 1];
        float p0 = 0.f, p1 = 0.f, q0 = 0.f, q1 = 0.f;
#pragma unroll
        for (int m = 0; m < 2; m++) {
            size_t r = row0 + rowb + 16 * m + gid;
            float v00 = fmaxf(acc[m][na][0] + bias0, 0.f), v01 = fmaxf(acc[m][na][1] + bias1, 0.f);
            float v10 = fmaxf(acc[m][na][2] + bias0, 0.f), v11 = fmaxf(acc[m][na][3] + bias1, 0.f);
            unsigned hp, lp;
            packpair(v00, v01, hp, lp);
            g_hh[r * 128 + (cgg >> 1)] = hp; g_hl[r * 128 + (cgg >> 1)] = lp;
            packpair(v10, v11, hp, lp);
            g_hh[(r + 8) * 128 + (cgg >> 1)] = hp; g_hl[(r + 8) * 128 + (cgg >> 1)] = lp;
            p0 += v00 + v10; p1 += v01 + v11;
            q0 += v00 * v00 + v10 * v10; q1 += v01 * v01 + v11 * v11;
        }
#pragma unroll
        for (int off = 4; off <= 16; off <<= 1) {
            p0 += __shfl_xor_sync(0xffffffffu, p0, off);
            p1 += __shfl_xor_sync(0xffffffffu, p1, off);
            q0 += __shfl_xor_sync(0xffffffffu, q0, off);
            q1 += __shfl_xor_sync(0xffffffffu, q1, off);
        }
        if (gid == 0) {
            sums[wm * 128 + cg] = p0; sums[wm * 128 + cg + 1] = p1;
            sqs [wm * 128 + cg] = q0; sqs [wm * 128 + cg + 1] = q1;
        }
    }
    __syncthreads();
    if (t < 128) {
        g_psum[(cb * 128 + t) * NB1 + rb] = sums[t] + sums[128 + t];
        g_psq [(cb * 128 + t) * NB1 + rb] = sqs[t] + sqs[128 + t];
    }
}

// ------------------- K2: BN stats finalize -------------------
__global__ __launch_bounds__(256)
void k_stats(const float* __restrict__ gamma, const float* __restrict__ beta) {
    const int c = blockIdx.x, t = threadIdx.x;
    float s = 0.f, qq = 0.f;
    for (int i = t; i < NB1; i += 256) { s += g_psum[c * NB1 + i]; qq += g_psq[c * NB1 + i]; }
#pragma unroll
    for (int off = 16; off; off >>= 1) {
        s += __shfl_xor_sync(0xffffffffu, s, off);
        qq += __shfl_xor_sync(0xffffffffu, qq, off);
    }
    __shared__ float ss[8], sq[8];
    if ((t & 31) == 0) { ss[t >> 5] = s; sq[t >> 5] = qq; }
    __syncthreads();
    if (t == 0) {
        float S = 0.f, Q = 0.f;
#pragma unroll
        for (int wv = 0; wv < 8; wv++) { S += ss[wv]; Q += sq[wv]; }
        const float inv_n = 1.f / (float)BTOT;
        float mu = S * inv_n;
        float var = Q * inv_n - mu * mu;
        float rstd = rsqrtf(var + 1e-5f);
        float gg = gamma[c];
        g_A[c] = rstd * gg;
        g_Bb[c] = beta[c] - mu * rstd * gg;
    }
}

// ------------- K2b: fold BN into W2 (bf16 split) + b2' ---------------
__global__ __launch_bounds__(256)
void k_fold(const float* __restrict__ W2, const float* __restrict__ b2) {
    const int n = blockIdx.x, k = threadIdx.x;
    float sc = g_A[k] * W2[k * 128 + n];
    unsigned short h = bh16(sc);
    g_w2h[n * 256 + k] = h;
    g_w2l[n * 256 + k] = bh16(sc - bup(h));
    float p = g_Bb[k] * W2[k * 128 + n];
#pragma unroll
    for (int off = 16; off; off >>= 1) p += __shfl_xor_sync(0xffffffffu, p, off);
    __shared__ float red[8];
    if ((k & 31) == 0) red[k >> 5] = p;
    __syncthreads();
    if (k == 0) {
        float S = 0.f;
#pragma unroll
        for (int i = 0; i < 8; i++) S += red[i];
        g_b2p[n] = b2[n] + S;
    }
}

// -- K3: enc = tanh(h@W2'+b2'), tile 64x128, K-chunks of 64, fused softmax --
__global__ __launch_bounds__(256, 3)
void k_gemm2(const float* __restrict__ att) {
    extern __shared__ unsigned sm[];
    unsigned* Ahi = sm;            // [64][36]
    unsigned* Alo = sm + 2304;
    unsigned* Bhi = sm + 4608;     // [128][36]
    unsigned* Blo = sm + 9216;     // end 13824
    float* attS = (float*)(sm + 13824);   // [10][128]
    float* b2ps = (float*)(sm + 15104);   // [128]; total 15232 words
    float* encS = (float*)sm;             // alias [64][132] = 8448 words
    const int t = threadIdx.x, w = t >> 5, lane = t & 31;
    const int gid = lane >> 2, q = lane & 3;
    const int wm = w >> 2, wn = w & 3, rowb = wm * 32, colb = wn * 32;
    const size_t row0 = (size_t)blockIdx.x * 64;
    const unsigned* w2hw = (const unsigned*)g_w2h;
    const unsigned* w2lw = (const unsigned*)g_w2l;

    for (int i = t; i < 1280; i += 256) attS[i] = att[i];
    if (t < 128) b2ps[t] = g_b2p[t];

    float acc[2][4][4];
#pragma unroll
    for (int m = 0; m < 2; m++)
#pragma unroll
        for (int na = 0; na < 4; na++)
#pragma unroll
            for (int j = 0; j < 4; j++) acc[m][na][j] = 0.f;

    for (int kc = 0; kc < 4; kc++) {
        __syncthreads();
        for (int i = t; i < 512; i += 256) {
            int r = i >> 3, c8 = i & 7;
            cpa16(Ahi + r * 36 + c8 * 4, g_hh + (row0 + r) * 128 + kc * 32 + c8 * 4);
            cpa16(Alo + r * 36 + c8 * 4, g_hl + (row0 + r) * 128 + kc * 32 + c8 * 4);
        }
        CPCOMMIT;
        for (int i = t; i < 1024; i += 256) {
            int n = i >> 3, c8 = i & 7;
            size_t gi = (size_t)n * 128 + kc * 32 + c8 * 4;
            *(uint4*)(Bhi + n * 36 + c8 * 4) = *(const uint4*)(w2hw + gi);
            *(uint4*)(Blo + n * 36 + c8 * 4) = *(const uint4*)(w2lw + gi);
        }
        CPWAIT0;
        __syncthreads();
#pragma unroll
        for (int ks = 0; ks < 4; ks++) {
            unsigned ah[2][4], al[2][4];
#pragma unroll
            for (int m = 0; m < 2; m++) {
                int b = (rowb + 16 * m + gid) * 36 + ks * 8 + q;
                ah[m][0] = Ahi[b]; ah[m][1] = Ahi[b + 288]; ah[m][2] = Ahi[b + 4]; ah[m][3] = Ahi[b + 292];
                al[m][0] = Alo[b]; al[m][1] = Alo[b + 288]; al[m][2] = Alo[b + 4]; al[m][3] = Alo[b + 292];
            }
#pragma unroll
            for (int na = 0; na < 4; na++) {
                int bb = (colb + 8 * na + gid) * 36 + ks * 8 + q;
                unsigned bh[2] = {Bhi[bb], Bhi[bb + 4]};
                unsigned bl[2] = {Blo[bb], Blo[bb + 4]};
#pragma unroll
                for (int m = 0; m < 2; m++) {
                    mma16(acc[m][na], ah[m], bh);
                    mma16(acc[m][na], al[m], bh);
                    mma16(acc[m][na], ah[m], bl);
                }
            }
        }
    }
    __syncthreads();
#pragma unroll
    for (int na = 0; na < 4; na++) {
        int cl = colb + 8 * na + 2 * q;
        float bb0 = b2ps[cl], bb1 = b2ps[cl + 1];
#pragma unroll
        for (int m = 0; m < 2; m++) {
            int r = rowb + 16 * m + gid;
            float e00 = tanhf(acc[m][na][0] + bb0), e01 = tanhf(acc[m][na][1] + bb1);
            float e10 = tanhf(acc[m][na][2] + bb0), e11 = tanhf(acc[m][na][3] + bb1);
            encS[r * 132 + cl] = e00;       encS[r * 132 + cl + 1] = e01;
            encS[(r + 8) * 132 + cl] = e10; encS[(r + 8) * 132 + cl + 1] = e11;
            g_ench[(row0 + r) * 64 + (cl >> 1)]     = packh(e00, e01);
            g_ench[(row0 + r + 8) * 64 + (cl >> 1)] = packh(e10, e11);
        }
    }
    __syncthreads();
    for (int it = 0; it < 8; it++) {
        int r = w * 8 + it;
        float4 e4 = *(float4*)(encS + r * 132 + lane * 4);
        float d[10];
#pragma unroll
        for (int k = 0; k < 10; k++) {
            float4 aa = *(float4*)(attS + k * 128 + lane * 4);
            float dx = e4.x - aa.x, dy = e4.y - aa.y, dz = e4.z - aa.z, dw = e4.w - aa.w;
            float p = dx * dx + dy * dy + dz * dz + dw * dw;
#pragma unroll
            for (int off = 16; off; off >>= 1) p += __shfl_xor_sync(0xffffffffu, p, off);
            d[k] = sqrtf(p);
        }
        float dmin = d[0];
#pragma unroll
        for (int k = 1; k < 10; k++) dmin = fminf(dmin, d[k]);
        float s[10], Z = 0.f;
#pragma unroll
        for (int k = 0; k < 10; k++) { s[k] = expf(-2.f * (d[k] - dmin)); Z += s[k]; }
        float invZ = 1.f / Z;
#pragma unroll
        for (int k = 0; k < 10; k++)
            if (lane == k) g_s[(row0 + r) * 10 + k] = s[k] * invZ;
    }
}

// ------------- K4: fused experts (fp16 k16) + gated contraction ------------
__global__ __launch_bounds__(512, 2)
void k_fused(const float* __restrict__ be1, float* __restrict__ out) {
    extern __shared__ unsigned sm[];
    unsigned* Ae  = sm;                  // enc fp16 [128][68]
    unsigned* buf = sm + 8704;           // We1 [128][68] / eh [128][76]
    unsigned* B2  = sm + 18560;          // [16][76]
    float* sS  = (float*)(sm + 19776);   // [128][12]
    float* sBe = (float*)(sm + 21312);   // [128]; total 21440 words
    const int t = threadIdx.x, w = t >> 5, lane = t & 31;
    const int gid = lane >> 2, q = lane & 3;
    const int wm = w >> 2, wn = w & 3;
    const size_t row0 = (size_t)blockIdx.x * 128;

    for (int i = t; i < 2048; i += 512) {
        int r = i >> 4, c4 = i & 15;
        cpa16(Ae + r * 68 + c4 * 4, g_ench + (row0 + r) * 64 + c4 * 4);
    }
    CPCOMMIT;
    for (int i = t; i < 1280; i += 512) {
        int r = i / 10, k = i - r * 10;
        sS[r * 12 + k] = g_s[(row0 + r) * 10 + k];
    }

    float acc2[2][4];
#pragma unroll
    for (int nf = 0; nf < 2; nf++)
#pragma unroll
        for (int j = 0; j < 4; j++) acc2[nf][j] = 0.f;

    for (int g = 0; g < 5; g++) {
        __syncthreads();
        for (int i = t; i < 2048; i += 512) {
            int j = i >> 4, c4 = i & 15;
            cpa16(buf + j * 68 + c4 * 4, g_we1p + g * 8192 + j * 64 + c4 * 4);
        }
        CPCOMMIT;
        if (t < 128) sBe[t] = be1[g * 128 + t];
        for (int i = t; i < 304; i += 512)
            ((uint4*)B2)[i] = ((const uint4*)(g_w2c + g * 1216))[i];
        CPWAIT0;
        __syncthreads();

        float acc[2][4][4];
#pragma unroll
        for (int m = 0; m < 2; m++)
#pragma unroll
            for (int na = 0; na < 4; na++)
#pragma unroll
                for (int j = 0; j < 4; j++) acc[m][na][j] = 0.f;
#pragma unroll
        for (int ks = 0; ks < 8; ks++) {
            unsigned a[2][4];
#pragma unroll
            for (int m = 0; m < 2; m++) {
                int b = (wm * 32 + 16 * m + gid) * 68 + ks * 8 + q;
                a[m][0] = Ae[b]; a[m][1] = Ae[b + 544]; a[m][2] = Ae[b + 4]; a[m][3] = Ae[b + 548];
            }
#pragma unroll
            for (int na = 0; na < 4; na++) {
                int bb = (wn * 32 + 8 * na + gid) * 68 + ks * 8 + q;
                unsigned bh[2] = {buf[bb], buf[bb + 4]};
                mma16h(acc[0][na], a[0], bh);
                mma16h(acc[1][na], a[1], bh);
            }
        }
        __syncthreads();
#pragma unroll
        for (int na = 0; na < 4; na++) {
            int jc = wn * 32 + 8 * na + 2 * q, pw = wn * 16 + 4 * na + q;
            float bia0 = sBe[jc], bia1 = sBe[jc + 1];
            int k0 = 2 * g + (jc >> 6);
#pragma unroll
            for (int m = 0; m < 2; m++) {
                int rr = wm * 32 + 16 * m + gid;
                float s0 = sS[rr * 12 + k0], s1 = sS[(rr + 8) * 12 + k0];
                buf[rr * 76 + pw] = packh(fmaxf(acc[m][na][0] + bia0, 0.f) * s0,
                                          fmaxf(acc[m][na][1] + bia1, 0.f) * s0);
                buf[(rr + 8) * 76 + pw] = packh(fmaxf(acc[m][na][2] + bia0, 0.f) * s1,
                                                fmaxf(acc[m][na][3] + bia1, 0.f) * s1);
            }
        }
        for (int i = t; i < 1024; i += 512) {
            int r = i >> 3, pw = 64 + (i & 7);
            buf[r * 76 + pw] = (pw == 64) ? packh(sS[r * 12 + 2 * g], sS[r * 12 + 2 * g + 1]) : 0u;
        }
        __syncthreads();
        if (w < 8) {
#pragma unroll
            for (int ks = 0; ks < 9; ks++) {
                int b = (w * 16 + gid) * 76 + ks * 8 + q;
                unsigned a2[4] = {buf[b], buf[b + 608], buf[b + 4], buf[b + 612]};
#pragma unroll
                for (int nf = 0; nf < 2; nf++) {
                    int bb = (nf * 8 + gid) * 76 + ks * 8 + q;
                    unsigned bh[2] = {B2[bb], B2[bb + 4]};
                    mma16h(acc2[nf], a2, bh);
                }
            }
        }
    }
    if (w < 8) {
        size_t r = row0 + w * 16 + gid;
        out[r * 10 + 2 * q]           = acc2[0][0];
        out[r * 10 + 2 * q + 1]       = acc2[0][1];
        out[(r + 8) * 10 + 2 * q]     = acc2[0][2];
        out[(r + 8) * 10 + 2 * q + 1] = acc2[0][3];
        if (q == 0) {
            out[r * 10 + 8] = acc2[1][0];       out[r * 10 + 9] = acc2[1][1];
            out[(r + 8) * 10 + 8] = acc2[1][2]; out[(r + 8) * 10 + 9] = acc2[1][3];
        }
    }
}

// ---------------------------------------------------------------------------
extern "C" void kernel_launch(void* const* d_in, const int* in_sizes, int n_in,
                              void* d_out, int out_size) {
    const float* state = (const float*)d_in[0];
    const float* W1    = (const float*)d_in[1];
    const float* b1    = (const float*)d_in[2];
    const float* gamma = (const float*)d_in[3];
    const float* beta  = (const float*)d_in[4];
    const float* W2    = (const float*)d_in[5];
    const float* b2    = (const float*)d_in[6];
    const float* We1   = (const float*)d_in[7];
    const float* be1   = (const float*)d_in[8];
    const float* We2   = (const float*)d_in[9];
    const float* be2   = (const float*)d_in[10];
    const float* att   = (const float*)d_in[11];
    float* out = (float*)d_out;

    const int SM1 = 13824 * 4, SM2 = 15232 * 4, SMF = 21440 * 4;
    cudaFuncSetAttribute(k_gemm1, cudaFuncAttributeMaxDynamicSharedMemorySize, SM1);
    cudaFuncSetAttribute(k_gemm2, cudaFuncAttributeMaxDynamicSharedMemorySize, SM2);
    cudaFuncSetAttribute(k_fused, cudaFuncAttributeMaxDynamicSharedMemorySize, SMF);

    k_prep <<<256, 256>>>(W1, We1, We2, be2);
    k_gemm1<<<dim3(NB1, 2), 256, SM1>>>(state, b1);
    k_stats<<<256, 256>>>(gamma, beta);
    k_fold <<<128, 256>>>(W2, b2);
    k_gemm2<<<NB1, 256, SM2>>>(att);
    k_fused<<<NBF, 512, SMF>>>(be1, out);
}

// round 10
// speedup vs baseline: 1.3320x; 1.1263x over previous
#include <cuda_runtime.h>
#include <cuda_fp16.h>
#include <math.h>

#define BTOT 262144
#define NB1  4096   // gemm1/gemm2 row blocks (64 rows)
#define NBF  2048   // fused row blocks (128 rows)

__device__ unsigned g_hh[(size_t)BTOT * 128];   // h fp16-hi pairs
__device__ unsigned g_hl[(size_t)BTOT * 128];   // h fp16-lo pairs
__device__ unsigned g_ench[(size_t)BTOT * 64];  // enc fp16 pairs
__device__ float    g_s[(size_t)BTOT * 10];
__device__ float    g_psum[256 * NB1];
__device__ float    g_psq [256 * NB1];
__device__ float    g_A[256], g_Bb[256], g_b2p[128];
__device__ unsigned g_w1p[256 * 64];            // W1 fp16 pairs [n][pw], k pad 128
__device__ unsigned short g_w2f[128 * 256];     // W2' fp16 [n][k]
__device__ unsigned g_we1p[5 * 128 * 64];
__device__ unsigned g_w2c [5 * 16 * 76];

__device__ __forceinline__ void mma16h(float* c, const unsigned* a, const unsigned* b) {
    asm volatile("mma.sync.aligned.m16n8k16.row.col.f32.f16.f16.f32 "
        "{%0,%1,%2,%3},{%4,%5,%6,%7},{%8,%9},{%0,%1,%2,%3};"
        : "+f"(c[0]), "+f"(c[1]), "+f"(c[2]), "+f"(c[3])
        : "r"(a[0]), "r"(a[1]), "r"(a[2]), "r"(a[3]), "r"(b[0]), "r"(b[1]));
}
__device__ __forceinline__ unsigned packh(float a, float b) {
    __half2 h = __floats2half2_rn(a, b); return *(unsigned*)&h;
}
// split v -> fp16 hi + fp16 residual lo (A-side 2-term split, ~22-bit mantissa)
__device__ __forceinline__ void packpairh(float v0, float v1, unsigned& hp, unsigned& lp) {
    __half h0 = __float2half_rn(v0), h1 = __float2half_rn(v1);
    hp = (unsigned)*(unsigned short*)&h0 | ((unsigned)*(unsigned short*)&h1 << 16);
    lp = packh(v0 - __half2float(h0), v1 - __half2float(h1));
}
__device__ __forceinline__ void cpa16(void* dst, const void* src) {
    unsigned d = (unsigned)__cvta_generic_to_shared(dst);
    asm volatile("cp.async.cg.shared.global [%0],[%1],16;\n" :: "r"(d), "l"(src));
}
#define CPCOMMIT asm volatile("cp.async.commit_group;\n")
#define CPWAIT0  asm volatile("cp.async.wait_group 0;\n")

// ------------------- prep -------------------
__global__ void k_prep(const float* __restrict__ W1, const float* __restrict__ We1,
                       const float* __restrict__ We2, const float* __restrict__ be2) {
    int idx = blockIdx.x * blockDim.x + threadIdx.x, st = gridDim.x * blockDim.x;
    for (int i = idx; i < 256 * 64; i += st) {
        int n = i >> 6, pw = i & 63;
        int k0 = 2 * pw, k1 = 2 * pw + 1;
        float v0 = (k0 < 100) ? W1[k0 * 256 + n] : 0.f;
        float v1 = (k1 < 100) ? W1[k1 * 256 + n] : 0.f;
        g_w1p[i] = packh(v0, v1);
    }
    for (int i = idx; i < 5 * 128 * 64; i += st) {
        int g = i >> 13, r = i & 8191, j = r >> 6, ep = r & 63;
        int sub = j >> 6, jl = j & 63;
        float v0 = We1[((size_t)(2 * g + sub) * 128 + 2 * ep) * 64 + jl];
        float v1 = We1[((size_t)(2 * g + sub) * 128 + 2 * ep + 1) * 64 + jl];
        g_we1p[i] = packh(v0, v1);
    }
    for (int i = idx; i < 5 * 16 * 76; i += st) {
        int g = i / 1216, r = i - g * 1216, a = r / 76, pw = r - a * 76;
        float v0 = 0.f, v1 = 0.f;
        if (a < 10) {
            if (pw < 64) {
                int j0 = 2 * pw, j1 = 2 * pw + 1;
                v0 = We2[(size_t)((2 * g + (j0 >> 6)) * 64 + (j0 & 63)) * 10 + a];
                v1 = We2[(size_t)((2 * g + (j1 >> 6)) * 64 + (j1 & 63)) * 10 + a];
            } else if (pw == 64) {
                v0 = be2[2 * g * 10 + a]; v1 = be2[(2 * g + 1) * 10 + a];
            }
        }
        g_w2c[i] = packh(v0, v1);
    }
}

// -- K1: h = relu(state@W1+b1). fp16 2-term A-split, single fp16 B, K=112. --
// grid (NB1, 2): rb = row block (64 rows), cb = col half (128 cols).
__global__ __launch_bounds__(256, 3)
void k_gemm1(const float* __restrict__ state, const float* __restrict__ b1) {
    extern __shared__ unsigned sm[];
    unsigned* Ahi = sm;            // [64][36]
    unsigned* Alo = sm + 2304;
    unsigned* Bs  = sm + 4608;     // [128][36]; end 9216 words
    const int t = threadIdx.x, w = t >> 5, lane = t & 31;
    const int gid = lane >> 2, q = lane & 3;
    const int wm = w >> 2, wn = w & 3, rowb = wm * 32, colb = wn * 32;
    const int rb = blockIdx.x, cb = blockIdx.y;
    const size_t row0 = (size_t)rb * 64;

    float acc[2][4][4];
#pragma unroll
    for (int m = 0; m < 2; m++)
#pragma unroll
        for (int na = 0; na < 4; na++)
#pragma unroll
            for (int j = 0; j < 4; j++) acc[m][na][j] = 0.f;

    for (int kc = 0; kc < 2; kc++) {
        __syncthreads();
        {   // A pack: 64 rows x 64 k (zeros past 100)
            int r = t >> 2, sl = t & 3, c0 = kc * 64 + sl * 16;
            float vv[16];
#pragma unroll
            for (int u = 0; u < 4; u++) {
                int k = c0 + u * 4;
                float4 x = (k < 100) ? *(const float4*)(state + (row0 + r) * 100 + k)
                                     : make_float4(0.f, 0.f, 0.f, 0.f);
                vv[4 * u] = x.x; vv[4 * u + 1] = x.y; vv[4 * u + 2] = x.z; vv[4 * u + 3] = x.w;
            }
            unsigned H[8], L[8];
#pragma unroll
            for (int u = 0; u < 8; u++) packpairh(vv[2 * u], vv[2 * u + 1], H[u], L[u]);
            *(uint4*)(Ahi + r * 36 + sl * 8)     = make_uint4(H[0], H[1], H[2], H[3]);
            *(uint4*)(Ahi + r * 36 + sl * 8 + 4) = make_uint4(H[4], H[5], H[6], H[7]);
            *(uint4*)(Alo + r * 36 + sl * 8)     = make_uint4(L[0], L[1], L[2], L[3]);
            *(uint4*)(Alo + r * 36 + sl * 8 + 4) = make_uint4(L[4], L[5], L[6], L[7]);
        }
        for (int i = t; i < 1024; i += 256) {
            int n = i >> 3, c8 = i & 7;
            *(uint4*)(Bs + n * 36 + c8 * 4) =
                *(const uint4*)(g_w1p + (size_t)(cb * 128 + n) * 64 + kc * 32 + c8 * 4);
        }
        __syncthreads();
        const int kcnt = kc ? 3 : 4;   // K = 64 + 48 = 112 (state real 100)
        for (int ks = 0; ks < kcnt; ks++) {
            unsigned ah[2][4], al[2][4];
#pragma unroll
            for (int m = 0; m < 2; m++) {
                int b = (rowb + 16 * m + gid) * 36 + ks * 8 + q;
                ah[m][0] = Ahi[b]; ah[m][1] = Ahi[b + 288]; ah[m][2] = Ahi[b + 4]; ah[m][3] = Ahi[b + 292];
                al[m][0] = Alo[b]; al[m][1] = Alo[b + 288]; al[m][2] = Alo[b + 4]; al[m][3] = Alo[b + 292];
            }
#pragma unroll
            for (int na = 0; na < 4; na++) {
                int bb = (colb + 8 * na + gid) * 36 + ks * 8 + q;
                unsigned bh[2] = {Bs[bb], Bs[bb + 4]};
#pragma unroll
                for (int m = 0; m < 2; m++) {
                    mma16h(acc[m][na], ah[m], bh);
                    mma16h(acc[m][na], al[m], bh);
                }
            }
        }
    }
    __syncthreads();
    float* sums = (float*)sm;     // [2][128]
    float* sqs  = sums + 256;
#pragma unroll
    for (int na = 0; na < 4; na++) {
        int cg = colb + 8 * na + 2 * q, cgg = cb * 128 + cg;
        float bias0 = b1[cgg], bias1 = b1[cgg + 1];
        float p0 = 0.f, p1 = 0.f, q0 = 0.f, q1 = 0.f;
#pragma unroll
        for (int m = 0; m < 2; m++) {
            size_t r = row0 + rowb + 16 * m + gid;
            float v00 = fmaxf(acc[m][na][0] + bias0, 0.f), v01 = fmaxf(acc[m][na][1] + bias1, 0.f);
            float v10 = fmaxf(acc[m][na][2] + bias0, 0.f), v11 = fmaxf(acc[m][na][3] + bias1, 0.f);
            unsigned hp, lp;
            packpairh(v00, v01, hp, lp);
            g_hh[r * 128 + (cgg >> 1)] = hp; g_hl[r * 128 + (cgg >> 1)] = lp;
            packpairh(v10, v11, hp, lp);
            g_hh[(r + 8) * 128 + (cgg >> 1)] = hp; g_hl[(r + 8) * 128 + (cgg >> 1)] = lp;
            p0 += v00 + v10; p1 += v01 + v11;
            q0 += v00 * v00 + v10 * v10; q1 += v01 * v01 + v11 * v11;
        }
#pragma unroll
        for (int off = 4; off <= 16; off <<= 1) {
            p0 += __shfl_xor_sync(0xffffffffu, p0, off);
            p1 += __shfl_xor_sync(0xffffffffu, p1, off);
            q0 += __shfl_xor_sync(0xffffffffu, q0, off);
            q1 += __shfl_xor_sync(0xffffffffu, q1, off);
        }
        if (gid == 0) {
            sums[wm * 128 + cg] = p0; sums[wm * 128 + cg + 1] = p1;
            sqs [wm * 128 + cg] = q0; sqs [wm * 128 + cg + 1] = q1;
        }
    }
    __syncthreads();
    if (t < 128) {
        g_psum[(cb * 128 + t) * NB1 + rb] = sums[t] + sums[128 + t];
        g_psq [(cb * 128 + t) * NB1 + rb] = sqs[t] + sqs[128 + t];
    }
}

// ------------------- K2: BN stats finalize -------------------
__global__ __launch_bounds__(256)
void k_stats(const float* __restrict__ gamma, const float* __restrict__ beta) {
    const int c = blockIdx.x, t = threadIdx.x;
    float s = 0.f, qq = 0.f;
    for (int i = t; i < NB1; i += 256) { s += g_psum[c * NB1 + i]; qq += g_psq[c * NB1 + i]; }
#pragma unroll
    for (int off = 16; off; off >>= 1) {
        s += __shfl_xor_sync(0xffffffffu, s, off);
        qq += __shfl_xor_sync(0xffffffffu, qq, off);
    }
    __shared__ float ss[8], sq[8];
    if ((t & 31) == 0) { ss[t >> 5] = s; sq[t >> 5] = qq; }
    __syncthreads();
    if (t == 0) {
        float S = 0.f, Q = 0.f;
#pragma unroll
        for (int wv = 0; wv < 8; wv++) { S += ss[wv]; Q += sq[wv]; }
        const float inv_n = 1.f / (float)BTOT;
        float mu = S * inv_n;
        float var = Q * inv_n - mu * mu;
        float rstd = rsqrtf(var + 1e-5f);
        float gg = gamma[c];
        g_A[c] = rstd * gg;
        g_Bb[c] = beta[c] - mu * rstd * gg;
    }
}

// ------------- K2b: fold BN into W2 (fp16 single) + b2' ---------------
__global__ __launch_bounds__(256)
void k_fold(const float* __restrict__ W2, const float* __restrict__ b2) {
    const int n = blockIdx.x, k = threadIdx.x;
    float wv = W2[k * 128 + n];
    __half hf = __float2half_rn(g_A[k] * wv);
    g_w2f[n * 256 + k] = *(unsigned short*)&hf;
    float p = g_Bb[k] * wv;
#pragma unroll
    for (int off = 16; off; off >>= 1) p += __shfl_xor_sync(0xffffffffu, p, off);
    __shared__ float red[8];
    if ((k & 31) == 0) red[k >> 5] = p;
    __syncthreads();
    if (k == 0) {
        float S = 0.f;
#pragma unroll
        for (int i = 0; i < 8; i++) S += red[i];
        g_b2p[n] = b2[n] + S;
    }
}

// -- K3: enc = tanh(h@W2'+b2'), fp16 2-term A-split, fused softmax ----------
__global__ __launch_bounds__(256, 3)
void k_gemm2(const float* __restrict__ att) {
    extern __shared__ unsigned sm[];
    unsigned* Ahi = sm;            // [64][36]
    unsigned* Alo = sm + 2304;
    unsigned* Bs  = sm + 4608;     // [128][36]; end 9216
    float* attS = (float*)(sm + 9216);    // [10][128]
    float* b2ps = (float*)(sm + 10496);   // [128]; total 10624 words
    float* encS = (float*)sm;             // alias [64][132] = 8448 words
    const int t = threadIdx.x, w = t >> 5, lane = t & 31;
    const int gid = lane >> 2, q = lane & 3;
    const int wm = w >> 2, wn = w & 3, rowb = wm * 32, colb = wn * 32;
    const size_t row0 = (size_t)blockIdx.x * 64;
    const unsigned* w2w = (const unsigned*)g_w2f;

    for (int i = t; i < 1280; i += 256) attS[i] = att[i];
    if (t < 128) b2ps[t] = g_b2p[t];

    float acc[2][4][4];
#pragma unroll
    for (int m = 0; m < 2; m++)
#pragma unroll
        for (int na = 0; na < 4; na++)
#pragma unroll
            for (int j = 0; j < 4; j++) acc[m][na][j] = 0.f;

    for (int kc = 0; kc < 4; kc++) {
        __syncthreads();
        for (int i = t; i < 512; i += 256) {
            int r = i >> 3, c8 = i & 7;
            cpa16(Ahi + r * 36 + c8 * 4, g_hh + (row0 + r) * 128 + kc * 32 + c8 * 4);
            cpa16(Alo + r * 36 + c8 * 4, g_hl + (row0 + r) * 128 + kc * 32 + c8 * 4);
        }
        CPCOMMIT;
        for (int i = t; i < 1024; i += 256) {
            int n = i >> 3, c8 = i & 7;
            *(uint4*)(Bs + n * 36 + c8 * 4) = *(const uint4*)(w2w + (size_t)n * 128 + kc * 32 + c8 * 4);
        }
        CPWAIT0;
        __syncthreads();
#pragma unroll
        for (int ks = 0; ks < 4; ks++) {
            unsigned ah[2][4], al[2][4];
#pragma unroll
            for (int m = 0; m < 2; m++) {
                int b = (rowb + 16 * m + gid) * 36 + ks * 8 + q;
                ah[m][0] = Ahi[b]; ah[m][1] = Ahi[b + 288]; ah[m][2] = Ahi[b + 4]; ah[m][3] = Ahi[b + 292];
                al[m][0] = Alo[b]; al[m][1] = Alo[b + 288]; al[m][2] = Alo[b + 4]; al[m][3] = Alo[b + 292];
            }
#pragma unroll
            for (int na = 0; na < 4; na++) {
                int bb = (colb + 8 * na + gid) * 36 + ks * 8 + q;
                unsigned bh[2] = {Bs[bb], Bs[bb + 4]};
#pragma unroll
                for (int m = 0; m < 2; m++) {
                    mma16h(acc[m][na], ah[m], bh);
                    mma16h(acc[m][na], al[m], bh);
                }
            }
        }
    }
    __syncthreads();
#pragma unroll
    for (int na = 0; na < 4; na++) {
        int cl = colb + 8 * na + 2 * q;
        float bb0 = b2ps[cl], bb1 = b2ps[cl + 1];
#pragma unroll
        for (int m = 0; m < 2; m++) {
            int r = rowb + 16 * m + gid;
            float e00 = tanhf(acc[m][na][0] + bb0), e01 = tanhf(acc[m][na][1] + bb1);
            float e10 = tanhf(acc[m][na][2] + bb0), e11 = tanhf(acc[m][na][3] + bb1);
            encS[r * 132 + cl] = e00;       encS[r * 132 + cl + 1] = e01;
            encS[(r + 8) * 132 + cl] = e10; encS[(r + 8) * 132 + cl + 1] = e11;
            g_ench[(row0 + r) * 64 + (cl >> 1)]     = packh(e00, e01);
            g_ench[(row0 + r + 8) * 64 + (cl >> 1)] = packh(e10, e11);
        }
    }
    __syncthreads();
    for (int it = 0; it < 8; it++) {
        int r = w * 8 + it;
        float4 e4 = *(float4*)(encS + r * 132 + lane * 4);
        float d[10];
#pragma unroll
        for (int k = 0; k < 10; k++) {
            float4 aa = *(float4*)(attS + k * 128 + lane * 4);
            float dx = e4.x - aa.x, dy = e4.y - aa.y, dz = e4.z - aa.z, dw = e4.w - aa.w;
            float p = dx * dx + dy * dy + dz * dz + dw * dw;
#pragma unroll
            for (int off = 16; off; off >>= 1) p += __shfl_xor_sync(0xffffffffu, p, off);
            d[k] = sqrtf(p);
        }
        float dmin = d[0];
#pragma unroll
        for (int k = 1; k < 10; k++) dmin = fminf(dmin, d[k]);
        float s[10], Z = 0.f;
#pragma unroll
        for (int k = 0; k < 10; k++) { s[k] = expf(-2.f * (d[k] - dmin)); Z += s[k]; }
        float invZ = 1.f / Z;
#pragma unroll
        for (int k = 0; k < 10; k++)
            if (lane == k) g_s[(row0 + r) * 10 + k] = s[k] * invZ;
    }
}

// ------------- K4: fused experts (fp16 k16) + gated contraction ------------
__global__ __launch_bounds__(512, 2)
void k_fused(const float* __restrict__ be1, float* __restrict__ out) {
    extern __shared__ unsigned sm[];
    unsigned* Ae  = sm;                  // enc fp16 [128][68]
    unsigned* buf = sm + 8704;           // We1 [128][68] / eh [128][76]
    unsigned* B2  = sm + 18560;          // [16][76]
    float* sS  = (float*)(sm + 19776);   // [128][12]
    float* sBe = (float*)(sm + 21312);   // [128]; total 21440 words
    const int t = threadIdx.x, w = t >> 5, lane = t & 31;
    const int gid = lane >> 2, q = lane & 3;
    const int wm = w >> 2, wn = w & 3;
    const size_t row0 = (size_t)blockIdx.x * 128;

    for (int i = t; i < 2048; i += 512) {
        int r = i >> 4, c4 = i & 15;
        cpa16(Ae + r * 68 + c4 * 4, g_ench + (row0 + r) * 64 + c4 * 4);
    }
    CPCOMMIT;
    for (int i = t; i < 1280; i += 512) {
        int r = i / 10, k = i - r * 10;
        sS[r * 12 + k] = g_s[(row0 + r) * 10 + k];
    }

    float acc2[2][4];
#pragma unroll
    for (int nf = 0; nf < 2; nf++)
#pragma unroll
        for (int j = 0; j < 4; j++) acc2[nf][j] = 0.f;

    for (int g = 0; g < 5; g++) {
        __syncthreads();
        for (int i = t; i < 2048; i += 512) {
            int j = i >> 4, c4 = i & 15;
            cpa16(buf + j * 68 + c4 * 4, g_we1p + g * 8192 + j * 64 + c4 * 4);
        }
        CPCOMMIT;
        if (t < 128) sBe[t] = be1[g * 128 + t];
        for (int i = t; i < 304; i += 512)
            ((uint4*)B2)[i] = ((const uint4*)(g_w2c + g * 1216))[i];
        CPWAIT0;
        __syncthreads();

        float acc[2][4][4];
#pragma unroll
        for (int m = 0; m < 2; m++)
#pragma unroll
            for (int na = 0; na < 4; na++)
#pragma unroll
                for (int j = 0; j < 4; j++) acc[m][na][j] = 0.f;
#pragma unroll
        for (int ks = 0; ks < 8; ks++) {
            unsigned a[2][4];
#pragma unroll
            for (int m = 0; m < 2; m++) {
                int b = (wm * 32 + 16 * m + gid) * 68 + ks * 8 + q;
                a[m][0] = Ae[b]; a[m][1] = Ae[b + 544]; a[m][2] = Ae[b + 4]; a[m][3] = Ae[b + 548];
            }
#pragma unroll
            for (int na = 0; na < 4; na++) {
                int bb = (wn * 32 + 8 * na + gid) * 68 + ks * 8 + q;
                unsigned bh[2] = {buf[bb], buf[bb + 4]};
                mma16h(acc[0][na], a[0], bh);
                mma16h(acc[1][na], a[1], bh);
            }
        }
        __syncthreads();
#pragma unroll
        for (int na = 0; na < 4; na++) {
            int jc = wn * 32 + 8 * na + 2 * q, pw = wn * 16 + 4 * na + q;
            float bia0 = sBe[jc], bia1 = sBe[jc + 1];
            int k0 = 2 * g + (jc >> 6);
#pragma unroll
            for (int m = 0; m < 2; m++) {
                int rr = wm * 32 + 16 * m + gid;
                float s0 = sS[rr * 12 + k0], s1 = sS[(rr + 8) * 12 + k0];
                buf[rr * 76 + pw] = packh(fmaxf(acc[m][na][0] + bia0, 0.f) * s0,
                                          fmaxf(acc[m][na][1] + bia1, 0.f) * s0);
                buf[(rr + 8) * 76 + pw] = packh(fmaxf(acc[m][na][2] + bia0, 0.f) * s1,
                                                fmaxf(acc[m][na][3] + bia1, 0.f) * s1);
            }
        }
        for (int i = t; i < 1024; i += 512) {
            int r = i >> 3, pw = 64 + (i & 7);
            buf[r * 76 + pw] = (pw == 64) ? packh(sS[r * 12 + 2 * g], sS[r * 12 + 2 * g + 1]) : 0u;
        }
        __syncthreads();
        if (w < 8) {
#pragma unroll
            for (int ks = 0; ks < 9; ks++) {
                int b = (w * 16 + gid) * 76 + ks * 8 + q;
                unsigned a2[4] = {buf[b], buf[b + 608], buf[b + 4], buf[b + 612]};
#pragma unroll
                for (int nf = 0; nf < 2; nf++) {
                    int bb = (nf * 8 + gid) * 76 + ks * 8 + q;
                    unsigned bh[2] = {B2[bb], B2[bb + 4]};
                    mma16h(acc2[nf], a2, bh);
                }
            }
        }
    }
    if (w < 8) {
        size_t r = row0 + w * 16 + gid;
        out[r * 10 + 2 * q]           = acc2[0][0];
        out[r * 10 + 2 * q + 1]       = acc2[0][1];
        out[(r + 8) * 10 + 2 * q]     = acc2[0][2];
        out[(r + 8) * 10 + 2 * q + 1] = acc2[0][3];
        if (q == 0) {
            out[r * 10 + 8] = acc2[1][0];       out[r * 10 + 9] = acc2[1][1];
            out[(r + 8) * 10 + 8] = acc2[1][2]; out[(r + 8) * 10 + 9] = acc2[1][3];
        }
    }
}

// ---------------------------------------------------------------------------
extern "C" void kernel_launch(void* const* d_in, const int* in_sizes, int n_in,
                              void* d_out, int out_size) {
    const float* state = (const float*)d_in[0];
    const float* W1    = (const float*)d_in[1];
    const float* b1    = (const float*)d_in[2];
    const float* gamma = (const float*)d_in[3];
    const float* beta  = (const float*)d_in[4];
    const float* W2    = (const float*)d_in[5];
    const float* b2    = (const float*)d_in[6];
    const float* We1   = (const float*)d_in[7];
    const float* be1   = (const float*)d_in[8];
    const float* We2   = (const float*)d_in[9];
    const float* be2   = (const float*)d_in[10];
    const float* att   = (const float*)d_in[11];
    float* out = (float*)d_out;

    const int SM1 = 9216 * 4, SM2 = 10624 * 4, SMF = 21440 * 4;
    cudaFuncSetAttribute(k_gemm1, cudaFuncAttributeMaxDynamicSharedMemorySize, SM1);
    cudaFuncSetAttribute(k_gemm2, cudaFuncAttributeMaxDynamicSharedMemorySize, SM2);
    cudaFuncSetAttribute(k_fused, cudaFuncAttributeMaxDynamicSharedMemorySize, SMF);

    k_prep <<<256, 256>>>(W1, We1, We2, be2);
    k_gemm1<<<dim3(NB1, 2), 256, SM1>>>(state, b1);
    k_stats<<<256, 256>>>(gamma, beta);
    k_fold <<<128, 256>>>(W2, b2);
    k_gemm2<<<NB1, 256, SM2>>>(att);
    k_fused<<<NBF, 512, SMF>>>(be1, out);
}

// round 11
// speedup vs baseline: 1.6596x; 1.2460x over previous
#include <cuda_runtime.h>
#include <cuda_fp16.h>
#include <math.h>

#define BTOT 262144
#define NB1  4096   // gemm1/gemm2 row blocks (64 rows)
#define NBF  2048   // fused row blocks (128 rows)

__device__ unsigned g_hh[(size_t)BTOT * 128];   // h fp16-hi pairs
__device__ unsigned g_hl[(size_t)BTOT * 128];   // h fp16-lo pairs
__device__ unsigned g_ench[(size_t)BTOT * 64];  // enc fp16 pairs
__device__ float    g_s[(size_t)BTOT * 10];
__device__ float    g_psum[256 * NB1];
__device__ float    g_psq [256 * NB1];
__device__ float    g_A[256], g_Bb[256], g_b2p[128];
__device__ unsigned g_w1p[256 * 64];            // W1 fp16 pairs [n][pw]
__device__ unsigned short g_w2f[128 * 256];     // W2' fp16 [n][k]
__device__ unsigned g_we1p[5 * 128 * 64];       // We1 fp16 pairs
__device__ unsigned g_w2c [5 * 16 * 68];        // We2 fp16 pairs [g][a][j-pw]

__device__ __forceinline__ void mma16h(float* c, const unsigned* a, const unsigned* b) {
    asm volatile("mma.sync.aligned.m16n8k16.row.col.f32.f16.f16.f32 "
        "{%0,%1,%2,%3},{%4,%5,%6,%7},{%8,%9},{%0,%1,%2,%3};"
        : "+f"(c[0]), "+f"(c[1]), "+f"(c[2]), "+f"(c[3])
        : "r"(a[0]), "r"(a[1]), "r"(a[2]), "r"(a[3]), "r"(b[0]), "r"(b[1]));
}
__device__ __forceinline__ unsigned packh(float a, float b) {
    __half2 h = __floats2half2_rn(a, b); return *(unsigned*)&h;
}
__device__ __forceinline__ void packpairh(float v0, float v1, unsigned& hp, unsigned& lp) {
    __half h0 = __float2half_rn(v0), h1 = __float2half_rn(v1);
    hp = (unsigned)*(unsigned short*)&h0 | ((unsigned)*(unsigned short*)&h1 << 16);
    lp = packh(v0 - __half2float(h0), v1 - __half2float(h1));
}
__device__ __forceinline__ void cpa16(void* dst, const void* src) {
    unsigned d = (unsigned)__cvta_generic_to_shared(dst);
    asm volatile("cp.async.cg.shared.global [%0],[%1],16;\n" :: "r"(d), "l"(src));
}
#define CPCOMMIT asm volatile("cp.async.commit_group;\n")
#define CPWAIT0  asm volatile("cp.async.wait_group 0;\n")
#define CPWAIT1  asm volatile("cp.async.wait_group 1;\n")

// ------------------- prep -------------------
__global__ void k_prep(const float* __restrict__ W1, const float* __restrict__ We1,
                       const float* __restrict__ We2) {
    int idx = blockIdx.x * blockDim.x + threadIdx.x, st = gridDim.x * blockDim.x;
    for (int i = idx; i < 256 * 64; i += st) {
        int n = i >> 6, pw = i & 63;
        int k0 = 2 * pw, k1 = 2 * pw + 1;
        float v0 = (k0 < 100) ? W1[k0 * 256 + n] : 0.f;
        float v1 = (k1 < 100) ? W1[k1 * 256 + n] : 0.f;
        g_w1p[i] = packh(v0, v1);
    }
    for (int i = idx; i < 5 * 128 * 64; i += st) {
        int g = i >> 13, r = i & 8191, j = r >> 6, ep = r & 63;
        int sub = j >> 6, jl = j & 63;
        float v0 = We1[((size_t)(2 * g + sub) * 128 + 2 * ep) * 64 + jl];
        float v1 = We1[((size_t)(2 * g + sub) * 128 + 2 * ep + 1) * 64 + jl];
        g_we1p[i] = packh(v0, v1);
    }
    for (int i = idx; i < 5 * 16 * 68; i += st) {
        int g = i / 1088, r = i - g * 1088, a = r / 68, pw = r - a * 68;
        float v0 = 0.f, v1 = 0.f;
        if (a < 10 && pw < 64) {
            int j0 = 2 * pw, j1 = 2 * pw + 1;
            v0 = We2[(size_t)((2 * g + (j0 >> 6)) * 64 + (j0 & 63)) * 10 + a];
            v1 = We2[(size_t)((2 * g + (j1 >> 6)) * 64 + (j1 & 63)) * 10 + a];
        }
        g_w2c[i] = packh(v0, v1);
    }
}

// -- K1: h = relu(state@W1+b1). fp16 2-term A-split, single fp16 B, K=112. --
__global__ __launch_bounds__(256, 3)
void k_gemm1(const float* __restrict__ state, const float* __restrict__ b1) {
    extern __shared__ unsigned sm[];
    unsigned* Ahi = sm;            // [64][36]
    unsigned* Alo = sm + 2304;
    unsigned* Bs  = sm + 4608;     // [128][36]; end 9216 words
    const int t = threadIdx.x, w = t >> 5, lane = t & 31;
    const int gid = lane >> 2, q = lane & 3;
    const int wm = w >> 2, wn = w & 3, rowb = wm * 32, colb = wn * 32;
    const int rb = blockIdx.x, cb = blockIdx.y;
    const size_t row0 = (size_t)rb * 64;

    float acc[2][4][4];
#pragma unroll
    for (int m = 0; m < 2; m++)
#pragma unroll
        for (int na = 0; na < 4; na++)
#pragma unroll
            for (int j = 0; j < 4; j++) acc[m][na][j] = 0.f;

    for (int kc = 0; kc < 2; kc++) {
        __syncthreads();
        {
            int r = t >> 2, sl = t & 3, c0 = kc * 64 + sl * 16;
            float vv[16];
#pragma unroll
            for (int u = 0; u < 4; u++) {
                int k = c0 + u * 4;
                float4 x = (k < 100) ? *(const float4*)(state + (row0 + r) * 100 + k)
                                     : make_float4(0.f, 0.f, 0.f, 0.f);
                vv[4 * u] = x.x; vv[4 * u + 1] = x.y; vv[4 * u + 2] = x.z; vv[4 * u + 3] = x.w;
            }
            unsigned H[8], L[8];
#pragma unroll
            for (int u = 0; u < 8; u++) packpairh(vv[2 * u], vv[2 * u + 1], H[u], L[u]);
            *(uint4*)(Ahi + r * 36 + sl * 8)     = make_uint4(H[0], H[1], H[2], H[3]);
            *(uint4*)(Ahi + r * 36 + sl * 8 + 4) = make_uint4(H[4], H[5], H[6], H[7]);
            *(uint4*)(Alo + r * 36 + sl * 8)     = make_uint4(L[0], L[1], L[2], L[3]);
            *(uint4*)(Alo + r * 36 + sl * 8 + 4) = make_uint4(L[4], L[5], L[6], L[7]);
        }
        for (int i = t; i < 1024; i += 256) {
            int n = i >> 3, c8 = i & 7;
            *(uint4*)(Bs + n * 36 + c8 * 4) =
                *(const uint4*)(g_w1p + (size_t)(cb * 128 + n) * 64 + kc * 32 + c8 * 4);
        }
        __syncthreads();
        const int kcnt = kc ? 3 : 4;
        for (int ks = 0; ks < kcnt; ks++) {
            unsigned ah[2][4], al[2][4];
#pragma unroll
            for (int m = 0; m < 2; m++) {
                int b = (rowb + 16 * m + gid) * 36 + ks * 8 + q;
                ah[m][0] = Ahi[b]; ah[m][1] = Ahi[b + 288]; ah[m][2] = Ahi[b + 4]; ah[m][3] = Ahi[b + 292];
                al[m][0] = Alo[b]; al[m][1] = Alo[b + 288]; al[m][2] = Alo[b + 4]; al[m][3] = Alo[b + 292];
            }
#pragma unroll
            for (int na = 0; na < 4; na++) {
                int bb = (colb + 8 * na + gid) * 36 + ks * 8 + q;
                unsigned bh[2] = {Bs[bb], Bs[bb + 4]};
#pragma unroll
                for (int m = 0; m < 2; m++) {
                    mma16h(acc[m][na], ah[m], bh);
                    mma16h(acc[m][na], al[m], bh);
                }
            }
        }
    }
    __syncthreads();
    float* sums = (float*)sm;
    float* sqs  = sums + 256;
#pragma unroll
    for (int na = 0; na < 4; na++) {
        int cg = colb + 8 * na + 2 * q, cgg = cb * 128 + cg;
        float bias0 = b1[cgg], bias1 = b1[cgg + 1];
        float p0 = 0.f, p1 = 0.f, q0 = 0.f, q1 = 0.f;
#pragma unroll
        for (int m = 0; m < 2; m++) {
            size_t r = row0 + rowb + 16 * m + gid;
            float v00 = fmaxf(acc[m][na][0] + bias0, 0.f), v01 = fmaxf(acc[m][na][1] + bias1, 0.f);
            float v10 = fmaxf(acc[m][na][2] + bias0, 0.f), v11 = fmaxf(acc[m][na][3] + bias1, 0.f);
            unsigned hp, lp;
            packpairh(v00, v01, hp, lp);
            g_hh[r * 128 + (cgg >> 1)] = hp; g_hl[r * 128 + (cgg >> 1)] = lp;
            packpairh(v10, v11, hp, lp);
            g_hh[(r + 8) * 128 + (cgg >> 1)] = hp; g_hl[(r + 8) * 128 + (cgg >> 1)] = lp;
            p0 += v00 + v10; p1 += v01 + v11;
            q0 += v00 * v00 + v10 * v10; q1 += v01 * v01 + v11 * v11;
        }
#pragma unroll
        for (int off = 4; off <= 16; off <<= 1) {
            p0 += __shfl_xor_sync(0xffffffffu, p0, off);
            p1 += __shfl_xor_sync(0xffffffffu, p1, off);
            q0 += __shfl_xor_sync(0xffffffffu, q0, off);
            q1 += __shfl_xor_sync(0xffffffffu, q1, off);
        }
        if (gid == 0) {
            sums[wm * 128 + cg] = p0; sums[wm * 128 + cg + 1] = p1;
            sqs [wm * 128 + cg] = q0; sqs [wm * 128 + cg + 1] = q1;
        }
    }
    __syncthreads();
    if (t < 128) {
        g_psum[(cb * 128 + t) * NB1 + rb] = sums[t] + sums[128 + t];
        g_psq [(cb * 128 + t) * NB1 + rb] = sqs[t] + sqs[128 + t];
    }
}

// ------------------- K2: BN stats finalize -------------------
__global__ __launch_bounds__(256)
void k_stats(const float* __restrict__ gamma, const float* __restrict__ beta) {
    const int c = blockIdx.x, t = threadIdx.x;
    float s = 0.f, qq = 0.f;
    for (int i = t; i < NB1; i += 256) { s += g_psum[c * NB1 + i]; qq += g_psq[c * NB1 + i]; }
#pragma unroll
    for (int off = 16; off; off >>= 1) {
        s += __shfl_xor_sync(0xffffffffu, s, off);
        qq += __shfl_xor_sync(0xffffffffu, qq, off);
    }
    __shared__ float ss[8], sq[8];
    if ((t & 31) == 0) { ss[t >> 5] = s; sq[t >> 5] = qq; }
    __syncthreads();
    if (t == 0) {
        float S = 0.f, Q = 0.f;
#pragma unroll
        for (int wv = 0; wv < 8; wv++) { S += ss[wv]; Q += sq[wv]; }
        const float inv_n = 1.f / (float)BTOT;
        float mu = S * inv_n;
        float var = Q * inv_n - mu * mu;
        float rstd = rsqrtf(var + 1e-5f);
        float gg = gamma[c];
        g_A[c] = rstd * gg;
        g_Bb[c] = beta[c] - mu * rstd * gg;
    }
}

// ------------- K2b: fold BN into W2 (fp16) + b2' ---------------
__global__ __launch_bounds__(256)
void k_fold(const float* __restrict__ W2, const float* __restrict__ b2) {
    const int n = blockIdx.x, k = threadIdx.x;
    float wv = W2[k * 128 + n];
    __half hf = __float2half_rn(g_A[k] * wv);
    g_w2f[n * 256 + k] = *(unsigned short*)&hf;
    float p = g_Bb[k] * wv;
#pragma unroll
    for (int off = 16; off; off >>= 1) p += __shfl_xor_sync(0xffffffffu, p, off);
    __shared__ float red[8];
    if ((k & 31) == 0) red[k >> 5] = p;
    __syncthreads();
    if (k == 0) {
        float S = 0.f;
#pragma unroll
        for (int i = 0; i < 8; i++) S += red[i];
        g_b2p[n] = b2[n] + S;
    }
}

// -- K3: enc = tanh(h@W2'+b2'), A-prefetch; MMA-based distances + softmax ---
__global__ __launch_bounds__(256, 3)
void k_gemm2(const float* __restrict__ att) {
    extern __shared__ unsigned sm[];
    // A double buffer: buf b at b*4608 (Ahi) / b*4608+2304 (Alo)
    unsigned* Bs  = sm + 9216;     // [128][36]
    unsigned* atH = sm + 13824;    // [16][68]
    unsigned* atL = sm + 14912;    // [16][68]
    float* b2ps = (float*)(sm + 16000);  // [128]
    float* asqS = (float*)(sm + 16128);  // [16]; total 16144 words
    // phase-2 aliases
    unsigned* eH = sm;             // [64][68]
    unsigned* eL = sm + 4352;      // [64][68]
    float* dotS = (float*)(sm + 9216);   // [64][20]
    float* esqP = (float*)(sm + 10496);  // [4][64]
    const int t = threadIdx.x, w = t >> 5, lane = t & 31;
    const int gid = lane >> 2, q = lane & 3;
    const int wm = w >> 2, wn = w & 3, rowb = wm * 32, colb = wn * 32;
    const size_t row0 = (size_t)blockIdx.x * 64;
    const unsigned* w2w = (const unsigned*)g_w2f;

    for (int i = t; i < 1088; i += 256) {
        int n = i / 68, pw = i - n * 68;
        float v0 = 0.f, v1 = 0.f;
        if (n < 10 && pw < 64) { v0 = att[n * 128 + 2 * pw]; v1 = att[n * 128 + 2 * pw + 1]; }
        unsigned hp, lp;
        packpairh(v0, v1, hp, lp);
        atH[i] = hp; atL[i] = lp;
    }
    if (t < 128) b2ps[t] = g_b2p[t];
    if (t >= 128 && t < 144) {
        int k = t - 128;
        float a2 = 0.f;
        if (k < 10)
            for (int c = 0; c < 128; c++) { float x = att[k * 128 + c]; a2 += x * x; }
        asqS[k] = a2;
    }

    float acc[2][4][4];
#pragma unroll
    for (int m = 0; m < 2; m++)
#pragma unroll
        for (int na = 0; na < 4; na++)
#pragma unroll
            for (int j = 0; j < 4; j++) acc[m][na][j] = 0.f;

    // prefetch A chunk 0
    for (int i = t; i < 512; i += 256) {
        int r = i >> 3, c8 = i & 7;
        cpa16(sm + r * 36 + c8 * 4,        g_hh + (row0 + r) * 128 + c8 * 4);
        cpa16(sm + 2304 + r * 36 + c8 * 4, g_hl + (row0 + r) * 128 + c8 * 4);
    }
    CPCOMMIT;
    for (int kc = 0; kc < 4; kc++) {
        if (kc < 3) {
            unsigned* dst = sm + ((kc + 1) & 1) * 4608;
            for (int i = t; i < 512; i += 256) {
                int r = i >> 3, c8 = i & 7;
                cpa16(dst + r * 36 + c8 * 4,        g_hh + (row0 + r) * 128 + (kc + 1) * 32 + c8 * 4);
                cpa16(dst + 2304 + r * 36 + c8 * 4, g_hl + (row0 + r) * 128 + (kc + 1) * 32 + c8 * 4);
            }
            CPCOMMIT;
        }
        for (int i = t; i < 1024; i += 256) {
            int n = i >> 3, c8 = i & 7;
            *(uint4*)(Bs + n * 36 + c8 * 4) = *(const uint4*)(w2w + (size_t)n * 128 + kc * 32 + c8 * 4);
        }
        if (kc < 3) { CPWAIT1; } else { CPWAIT0; }
        __syncthreads();
        unsigned* Ahi = sm + (kc & 1) * 4608;
        unsigned* Alo = Ahi + 2304;
#pragma unroll
        for (int ks = 0; ks < 4; ks++) {
            unsigned ah[2][4], al[2][4];
#pragma unroll
            for (int m = 0; m < 2; m++) {
                int b = (rowb + 16 * m + gid) * 36 + ks * 8 + q;
                ah[m][0] = Ahi[b]; ah[m][1] = Ahi[b + 288]; ah[m][2] = Ahi[b + 4]; ah[m][3] = Ahi[b + 292];
                al[m][0] = Alo[b]; al[m][1] = Alo[b + 288]; al[m][2] = Alo[b + 4]; al[m][3] = Alo[b + 292];
            }
#pragma unroll
            for (int na = 0; na < 4; na++) {
                int bb = (colb + 8 * na + gid) * 36 + ks * 8 + q;
                unsigned bh[2] = {Bs[bb], Bs[bb + 4]};
#pragma unroll
                for (int m = 0; m < 2; m++) {
                    mma16h(acc[m][na], ah[m], bh);
                    mma16h(acc[m][na], al[m], bh);
                }
            }
        }
        __syncthreads();
    }
    // tanh epilogue: enc -> eH/eL smem + gmem hi; ||e||^2 partials
    float p2[4] = {0.f, 0.f, 0.f, 0.f};
#pragma unroll
    for (int na = 0; na < 4; na++) {
        int cl = colb + 8 * na + 2 * q, pw = (cl >> 1);
        float bb0 = b2ps[cl], bb1 = b2ps[cl + 1];
#pragma unroll
        for (int m = 0; m < 2; m++) {
            int r = rowb + 16 * m + gid;
            float e00 = tanhf(acc[m][na][0] + bb0), e01 = tanhf(acc[m][na][1] + bb1);
            float e10 = tanhf(acc[m][na][2] + bb0), e11 = tanhf(acc[m][na][3] + bb1);
            unsigned hp, lp;
            packpairh(e00, e01, hp, lp);
            eH[r * 68 + pw] = hp; eL[r * 68 + pw] = lp;
            g_ench[(row0 + r) * 64 + pw] = hp;
            packpairh(e10, e11, hp, lp);
            eH[(r + 8) * 68 + pw] = hp; eL[(r + 8) * 68 + pw] = lp;
            g_ench[(row0 + r + 8) * 64 + pw] = hp;
            p2[2 * m]     += e00 * e00 + e01 * e01;
            p2[2 * m + 1] += e10 * e10 + e11 * e11;
        }
    }
#pragma unroll
    for (int j = 0; j < 4; j++) {
        p2[j] += __shfl_xor_sync(0xffffffffu, p2[j], 1);
        p2[j] += __shfl_xor_sync(0xffffffffu, p2[j], 2);
    }
    if (q == 0) {
#pragma unroll
        for (int m = 0; m < 2; m++) {
            esqP[wn * 64 + rowb + 16 * m + gid]     = p2[2 * m];
            esqP[wn * 64 + rowb + 16 * m + gid + 8] = p2[2 * m + 1];
        }
    }
    __syncthreads();
    // dot = enc . att^T via 3-term fp16 MMA; warps: mt = w>>1 (4 m-tiles), nt = w&1
    {
        const int mt = w >> 1, nt = w & 1;
        float d4[4] = {0.f, 0.f, 0.f, 0.f};
#pragma unroll
        for (int term = 0; term < 3; term++) {
            const unsigned* Aop = (term == 1) ? eL : eH;
            const unsigned* Bop = (term == 2) ? atL : atH;
#pragma unroll
            for (int ks = 0; ks < 8; ks++) {
                int b = (mt * 16 + gid) * 68 + ks * 8 + q;
                unsigned a[4] = {Aop[b], Aop[b + 544], Aop[b + 4], Aop[b + 548]};
                int bb = (nt * 8 + gid) * 68 + ks * 8 + q;
                unsigned bh[2] = {Bop[bb], Bop[bb + 4]};
                mma16h(d4, a, bh);
            }
        }
        int r = mt * 16 + gid, cc = nt * 8 + 2 * q;
        dotS[r * 20 + cc] = d4[0];       dotS[r * 20 + cc + 1] = d4[1];
        dotS[(r + 8) * 20 + cc] = d4[2]; dotS[(r + 8) * 20 + cc + 1] = d4[3];
    }
    __syncthreads();
    if (t < 64) {
        float esqv = esqP[t] + esqP[64 + t] + esqP[128 + t] + esqP[192 + t];
        float d[10];
#pragma unroll
        for (int k = 0; k < 10; k++)
            d[k] = sqrtf(fmaxf(esqv - 2.f * dotS[t * 20 + k] + asqS[k], 0.f));
        float dmin = d[0];
#pragma unroll
        for (int k = 1; k < 10; k++) dmin = fminf(dmin, d[k]);
        float s[10], Z = 0.f;
#pragma unroll
        for (int k = 0; k < 10; k++) { s[k] = expf(-2.f * (d[k] - dmin)); Z += s[k]; }
        float invZ = 1.f / Z;
#pragma unroll
        for (int k = 0; k < 10; k++) g_s[(row0 + t) * 10 + k] = s[k] * invZ;
    }
}

// ------------- K4: fused experts (fp16 k16) + gated contraction ------------
__global__ __launch_bounds__(512, 2)
void k_fused(const float* __restrict__ be1, const float* __restrict__ be2,
             float* __restrict__ out) {
    extern __shared__ unsigned sm[];
    unsigned* Ae  = sm;                  // enc fp16 [128][68]
    unsigned* buf = sm + 8704;           // We1 [128][68] / eh [128][68]
    unsigned* B2  = sm + 17408;          // [16][68]
    float* sS   = (float*)(sm + 18496);  // [128][12]
    float* sBe  = (float*)(sm + 20032);  // [128]
    float* be2S = (float*)(sm + 20160);  // [100 used]; total 20288 words
    const int t = threadIdx.x, w = t >> 5, lane = t & 31;
    const int gid = lane >> 2, q = lane & 3;
    const int wm = w >> 2, wn = w & 3;
    const size_t row0 = (size_t)blockIdx.x * 128;

    for (int i = t; i < 2048; i += 512) {
        int r = i >> 4, c4 = i & 15;
        cpa16(Ae + r * 68 + c4 * 4, g_ench + (row0 + r) * 64 + c4 * 4);
    }
    CPCOMMIT;
    for (int i = t; i < 1280; i += 512) {
        int r = i / 10, k = i - r * 10;
        sS[r * 12 + k] = g_s[(row0 + r) * 10 + k];
    }
    if (t < 100) be2S[t] = be2[t];

    float acc2[2][4];
#pragma unroll
    for (int nf = 0; nf < 2; nf++)
#pragma unroll
        for (int j = 0; j < 4; j++) acc2[nf][j] = 0.f;

    for (int g = 0; g < 5; g++) {
        __syncthreads();
        for (int i = t; i < 2048; i += 512) {
            int j = i >> 4, c4 = i & 15;
            cpa16(buf + j * 68 + c4 * 4, g_we1p + g * 8192 + j * 64 + c4 * 4);
        }
        CPCOMMIT;
        if (t < 128) sBe[t] = be1[g * 128 + t];
        for (int i = t; i < 272; i += 512)
            ((uint4*)B2)[i] = ((const uint4*)(g_w2c + g * 1088))[i];
        CPWAIT0;
        __syncthreads();

        float acc[2][4][4];
#pragma unroll
        for (int m = 0; m < 2; m++)
#pragma unroll
            for (int na = 0; na < 4; na++)
#pragma unroll
                for (int j = 0; j < 4; j++) acc[m][na][j] = 0.f;
#pragma unroll
        for (int ks = 0; ks < 8; ks++) {
            unsigned a[2][4];
#pragma unroll
            for (int m = 0; m < 2; m++) {
                int b = (wm * 32 + 16 * m + gid) * 68 + ks * 8 + q;
                a[m][0] = Ae[b]; a[m][1] = Ae[b + 544]; a[m][2] = Ae[b + 4]; a[m][3] = Ae[b + 548];
            }
#pragma unroll
            for (int na = 0; na < 4; na++) {
                int bb = (wn * 32 + 8 * na + gid) * 68 + ks * 8 + q;
                unsigned bh[2] = {buf[bb], buf[bb + 4]};
                mma16h(acc[0][na], a[0], bh);
                mma16h(acc[1][na], a[1], bh);
            }
        }
        __syncthreads();
#pragma unroll
        for (int na = 0; na < 4; na++) {
            int jc = wn * 32 + 8 * na + 2 * q, pw = wn * 16 + 4 * na + q;
            float bia0 = sBe[jc], bia1 = sBe[jc + 1];
            int k0 = 2 * g + (jc >> 6);
#pragma unroll
            for (int m = 0; m < 2; m++) {
                int rr = wm * 32 + 16 * m + gid;
                float s0 = sS[rr * 12 + k0], s1 = sS[(rr + 8) * 12 + k0];
                buf[rr * 68 + pw] = packh(fmaxf(acc[m][na][0] + bia0, 0.f) * s0,
                                          fmaxf(acc[m][na][1] + bia1, 0.f) * s0);
                buf[(rr + 8) * 68 + pw] = packh(fmaxf(acc[m][na][2] + bia0, 0.f) * s1,
                                                fmaxf(acc[m][na][3] + bia1, 0.f) * s1);
            }
        }
        __syncthreads();
        if (w < 8) {
#pragma unroll
            for (int ks = 0; ks < 8; ks++) {
                int b = (w * 16 + gid) * 68 + ks * 8 + q;
                unsigned a2[4] = {buf[b], buf[b + 544], buf[b + 4], buf[b + 548]};
#pragma unroll
                for (int nf = 0; nf < 2; nf++) {
                    int bb = (nf * 8 + gid) * 68 + ks * 8 + q;
                    unsigned bh[2] = {B2[bb], B2[bb + 4]};
                    mma16h(acc2[nf], a2, bh);
                }
            }
        }
    }
    if (w < 8) {
        const int rl = w * 16 + gid;
        const size_t r = row0 + rl;
        float b0 = 0.f, b1 = 0.f, b2a = 0.f, b3 = 0.f;
        float c0 = 0.f, c1 = 0.f, c2 = 0.f, c3 = 0.f;
#pragma unroll
        for (int k = 0; k < 10; k++) {
            float s0 = sS[rl * 12 + k], s1 = sS[(rl + 8) * 12 + k];
            float w0 = be2S[k * 10 + 2 * q], w1 = be2S[k * 10 + 2 * q + 1];
            b0 += s0 * w0; b1 += s0 * w1; b2a += s1 * w0; b3 += s1 * w1;
            if (q == 0) {
                float w8 = be2S[k * 10 + 8], w9 = be2S[k * 10 + 9];
                c0 += s0 * w8; c1 += s0 * w9; c2 += s1 * w8; c3 += s1 * w9;
            }
        }
        out[r * 10 + 2 * q]           = acc2[0][0] + b0;
        out[r * 10 + 2 * q + 1]       = acc2[0][1] + b1;
        out[(r + 8) * 10 + 2 * q]     = acc2[0][2] + b2a;
        out[(r + 8) * 10 + 2 * q + 1] = acc2[0][3] + b3;
        if (q == 0) {
            out[r * 10 + 8] = acc2[1][0] + c0;       out[r * 10 + 9] = acc2[1][1] + c1;
            out[(r + 8) * 10 + 8] = acc2[1][2] + c2; out[(r + 8) * 10 + 9] = acc2[1][3] + c3;
        }
    }
}

// ---------------------------------------------------------------------------
extern "C" void kernel_launch(void* const* d_in, const int* in_sizes, int n_in,
                              void* d_out, int out_size) {
    const float* state = (const float*)d_in[0];
    const float* W1    = (const float*)d_in[1];
    const float* b1    = (const float*)d_in[2];
    const float* gamma = (const float*)d_in[3];
    const float* beta  = (const float*)d_in[4];
    const float* W2    = (const float*)d_in[5];
    const float* b2    = (const float*)d_in[6];
    const float* We1   = (const float*)d_in[7];
    const float* be1   = (const float*)d_in[8];
    const float* We2   = (const float*)d_in[9];
    const float* be2   = (const float*)d_in[10];
    const float* att   = (const float*)d_in[11];
    float* out = (float*)d_out;

    const int SM1 = 9216 * 4, SM2 = 16144 * 4, SMF = 20288 * 4;
    cudaFuncSetAttribute(k_gemm1, cudaFuncAttributeMaxDynamicSharedMemorySize, SM1);
    cudaFuncSetAttribute(k_gemm2, cudaFuncAttributeMaxDynamicSharedMemorySize, SM2);
    cudaFuncSetAttribute(k_fused, cudaFuncAttributeMaxDynamicSharedMemorySize, SMF);

    k_prep <<<256, 256>>>(W1, We1, We2);
    k_gemm1<<<dim3(NB1, 2), 256, SM1>>>(state, b1);
    k_stats<<<256, 256>>>(gamma, beta);
    k_fold <<<128, 256>>>(W2, b2);
    k_gemm2<<<NB1, 256, SM2>>>(att);
    k_fused<<<NBF, 512, SMF>>>(be1, be2, out);
}

// round 12
// speedup vs baseline: 2.0015x; 1.2060x over previous
#include <cuda_runtime.h>
#include <cuda_fp16.h>
#include <math.h>

#define BTOT 262144
#define NB1  4096   // gemm1/gemm2 row blocks (64 rows)
#define NBF  2048   // fused row blocks (128 rows)

__device__ unsigned g_hh[(size_t)BTOT * 128];   // h fp16 pairs
__device__ unsigned g_ench[(size_t)BTOT * 64];  // enc fp16 pairs
__device__ float    g_s[(size_t)BTOT * 10];
__device__ float    g_psum[256 * NB1];
__device__ float    g_psq [256 * NB1];
__device__ float    g_A[256], g_Bb[256], g_b2p[128];
__device__ unsigned g_w1p[256 * 64];            // W1 fp16 pairs [n][pw]
__device__ unsigned short g_w2f[128 * 256];     // W2' fp16 [n][k]
__device__ unsigned g_we1p[5 * 128 * 64];       // We1 fp16 pairs
__device__ unsigned g_w2c [5 * 16 * 68];        // We2 fp16 pairs [g][a][j-pw]

__device__ __forceinline__ void mma16h(float* c, const unsigned* a, const unsigned* b) {
    asm volatile("mma.sync.aligned.m16n8k16.row.col.f32.f16.f16.f32 "
        "{%0,%1,%2,%3},{%4,%5,%6,%7},{%8,%9},{%0,%1,%2,%3};"
        : "+f"(c[0]), "+f"(c[1]), "+f"(c[2]), "+f"(c[3])
        : "r"(a[0]), "r"(a[1]), "r"(a[2]), "r"(a[3]), "r"(b[0]), "r"(b[1]));
}
__device__ __forceinline__ unsigned packh(float a, float b) {
    __half2 h = __floats2half2_rn(a, b); return *(unsigned*)&h;
}
__device__ __forceinline__ void packpairh(float v0, float v1, unsigned& hp, unsigned& lp) {
    __half h0 = __float2half_rn(v0), h1 = __float2half_rn(v1);
    hp = (unsigned)*(unsigned short*)&h0 | ((unsigned)*(unsigned short*)&h1 << 16);
    lp = packh(v0 - __half2float(h0), v1 - __half2float(h1));
}
__device__ __forceinline__ void cpa16(void* dst, const void* src) {
    unsigned d = (unsigned)__cvta_generic_to_shared(dst);
    asm volatile("cp.async.cg.shared.global [%0],[%1],16;\n" :: "r"(d), "l"(src));
}
#define CPCOMMIT asm volatile("cp.async.commit_group;\n")
#define CPWAIT0  asm volatile("cp.async.wait_group 0;\n")
#define CPWAIT1  asm volatile("cp.async.wait_group 1;\n")

// ------------------- prep -------------------
__global__ void k_prep(const float* __restrict__ W1, const float* __restrict__ We1,
                       const float* __restrict__ We2) {
    int idx = blockIdx.x * blockDim.x + threadIdx.x, st = gridDim.x * blockDim.x;
    for (int i = idx; i < 256 * 64; i += st) {
        int n = i >> 6, pw = i & 63;
        int k0 = 2 * pw, k1 = 2 * pw + 1;
        float v0 = (k0 < 100) ? W1[k0 * 256 + n] : 0.f;
        float v1 = (k1 < 100) ? W1[k1 * 256 + n] : 0.f;
        g_w1p[i] = packh(v0, v1);
    }
    for (int i = idx; i < 5 * 128 * 64; i += st) {
        int g = i >> 13, r = i & 8191, j = r >> 6, ep = r & 63;
        int sub = j >> 6, jl = j & 63;
        float v0 = We1[((size_t)(2 * g + sub) * 128 + 2 * ep) * 64 + jl];
        float v1 = We1[((size_t)(2 * g + sub) * 128 + 2 * ep + 1) * 64 + jl];
        g_we1p[i] = packh(v0, v1);
    }
    for (int i = idx; i < 5 * 16 * 68; i += st) {
        int g = i / 1088, r = i - g * 1088, a = r / 68, pw = r - a * 68;
        float v0 = 0.f, v1 = 0.f;
        if (a < 10 && pw < 64) {
            int j0 = 2 * pw, j1 = 2 * pw + 1;
            v0 = We2[(size_t)((2 * g + (j0 >> 6)) * 64 + (j0 & 63)) * 10 + a];
            v1 = We2[(size_t)((2 * g + (j1 >> 6)) * 64 + (j1 & 63)) * 10 + a];
        }
        g_w2c[i] = packh(v0, v1);
    }
}

// -- K1: h = relu(state@W1+b1). single fp16 A and B, K=112. -----------------
__global__ __launch_bounds__(256, 3)
void k_gemm1(const float* __restrict__ state, const float* __restrict__ b1) {
    extern __shared__ unsigned sm[];
    unsigned* As = sm;             // [64][36]
    unsigned* Bs = sm + 2304;      // [128][36]; end 6912 words
    const int t = threadIdx.x, w = t >> 5, lane = t & 31;
    const int gid = lane >> 2, q = lane & 3;
    const int wm = w >> 2, wn = w & 3, rowb = wm * 32, colb = wn * 32;
    const int rb = blockIdx.x, cb = blockIdx.y;
    const size_t row0 = (size_t)rb * 64;

    float acc[2][4][4];
#pragma unroll
    for (int m = 0; m < 2; m++)
#pragma unroll
        for (int na = 0; na < 4; na++)
#pragma unroll
            for (int j = 0; j < 4; j++) acc[m][na][j] = 0.f;

    for (int kc = 0; kc < 2; kc++) {
        __syncthreads();
        {
            int r = t >> 2, sl = t & 3, c0 = kc * 64 + sl * 16;
            float vv[16];
#pragma unroll
            for (int u = 0; u < 4; u++) {
                int k = c0 + u * 4;
                float4 x = (k < 100) ? *(const float4*)(state + (row0 + r) * 100 + k)
                                     : make_float4(0.f, 0.f, 0.f, 0.f);
                vv[4 * u] = x.x; vv[4 * u + 1] = x.y; vv[4 * u + 2] = x.z; vv[4 * u + 3] = x.w;
            }
            unsigned H[8];
#pragma unroll
            for (int u = 0; u < 8; u++) H[u] = packh(vv[2 * u], vv[2 * u + 1]);
            *(uint4*)(As + r * 36 + sl * 8)     = make_uint4(H[0], H[1], H[2], H[3]);
            *(uint4*)(As + r * 36 + sl * 8 + 4) = make_uint4(H[4], H[5], H[6], H[7]);
        }
        for (int i = t; i < 1024; i += 256) {
            int n = i >> 3, c8 = i & 7;
            *(uint4*)(Bs + n * 36 + c8 * 4) =
                *(const uint4*)(g_w1p + (size_t)(cb * 128 + n) * 64 + kc * 32 + c8 * 4);
        }
        __syncthreads();
        const int kcnt = kc ? 3 : 4;
        for (int ks = 0; ks < kcnt; ks++) {
            unsigned ah[2][4];
#pragma unroll
            for (int m = 0; m < 2; m++) {
                int b = (rowb + 16 * m + gid) * 36 + ks * 8 + q;
                ah[m][0] = As[b]; ah[m][1] = As[b + 288]; ah[m][2] = As[b + 4]; ah[m][3] = As[b + 292];
            }
#pragma unroll
            for (int na = 0; na < 4; na++) {
                int bb = (colb + 8 * na + gid) * 36 + ks * 8 + q;
                unsigned bh[2] = {Bs[bb], Bs[bb + 4]};
#pragma unroll
                for (int m = 0; m < 2; m++) mma16h(acc[m][na], ah[m], bh);
            }
        }
    }
    __syncthreads();
    float* sums = (float*)sm;
    float* sqs  = sums + 256;
#pragma unroll
    for (int na = 0; na < 4; na++) {
        int cg = colb + 8 * na + 2 * q, cgg = cb * 128 + cg;
        float bias0 = b1[cgg], bias1 = b1[cgg + 1];
        float p0 = 0.f, p1 = 0.f, q0 = 0.f, q1 = 0.f;
#pragma unroll
        for (int m = 0; m < 2; m++) {
            size_t r = row0 + rowb + 16 * m + gid;
            float v00 = fmaxf(acc[m][na][0] + bias0, 0.f), v01 = fmaxf(acc[m][na][1] + bias1, 0.f);
            float v10 = fmaxf(acc[m][na][2] + bias0, 0.f), v11 = fmaxf(acc[m][na][3] + bias1, 0.f);
            g_hh[r * 128 + (cgg >> 1)]       = packh(v00, v01);
            g_hh[(r + 8) * 128 + (cgg >> 1)] = packh(v10, v11);
            p0 += v00 + v10; p1 += v01 + v11;
            q0 += v00 * v00 + v10 * v10; q1 += v01 * v01 + v11 * v11;
        }
#pragma unroll
        for (int off = 4; off <= 16; off <<= 1) {
            p0 += __shfl_xor_sync(0xffffffffu, p0, off);
            p1 += __shfl_xor_sync(0xffffffffu, p1, off);
            q0 += __shfl_xor_sync(0xffffffffu, q0, off);
            q1 += __shfl_xor_sync(0xffffffffu, q1, off);
        }
        if (gid == 0) {
            sums[wm * 128 + cg] = p0; sums[wm * 128 + cg + 1] = p1;
            sqs [wm * 128 + cg] = q0; sqs [wm * 128 + cg + 1] = q1;
        }
    }
    __syncthreads();
    if (t < 128) {
        g_psum[(cb * 128 + t) * NB1 + rb] = sums[t] + sums[128 + t];
        g_psq [(cb * 128 + t) * NB1 + rb] = sqs[t] + sqs[128 + t];
    }
}

// ------------------- K2: BN stats finalize -------------------
__global__ __launch_bounds__(256)
void k_stats(const float* __restrict__ gamma, const float* __restrict__ beta) {
    const int c = blockIdx.x, t = threadIdx.x;
    float s = 0.f, qq = 0.f;
    for (int i = t; i < NB1; i += 256) { s += g_psum[c * NB1 + i]; qq += g_psq[c * NB1 + i]; }
#pragma unroll
    for (int off = 16; off; off >>= 1) {
        s += __shfl_xor_sync(0xffffffffu, s, off);
        qq += __shfl_xor_sync(0xffffffffu, qq, off);
    }
    __shared__ float ss[8], sq[8];
    if ((t & 31) == 0) { ss[t >> 5] = s; sq[t >> 5] = qq; }
    __syncthreads();
    if (t == 0) {
        float S = 0.f, Q = 0.f;
#pragma unroll
        for (int wv = 0; wv < 8; wv++) { S += ss[wv]; Q += sq[wv]; }
        const float inv_n = 1.f / (float)BTOT;
        float mu = S * inv_n;
        float var = Q * inv_n - mu * mu;
        float rstd = rsqrtf(var + 1e-5f);
        float gg = gamma[c];
        g_A[c] = rstd * gg;
        g_Bb[c] = beta[c] - mu * rstd * gg;
    }
}

// ------------- K2b: fold BN into W2 (fp16) + b2' ---------------
__global__ __launch_bounds__(256)
void k_fold(const float* __restrict__ W2, const float* __restrict__ b2) {
    const int n = blockIdx.x, k = threadIdx.x;
    float wv = W2[k * 128 + n];
    __half hf = __float2half_rn(g_A[k] * wv);
    g_w2f[n * 256 + k] = *(unsigned short*)&hf;
    float p = g_Bb[k] * wv;
#pragma unroll
    for (int off = 16; off; off >>= 1) p += __shfl_xor_sync(0xffffffffu, p, off);
    __shared__ float red[8];
    if ((k & 31) == 0) red[k >> 5] = p;
    __syncthreads();
    if (k == 0) {
        float S = 0.f;
#pragma unroll
        for (int i = 0; i < 8; i++) S += red[i];
        g_b2p[n] = b2[n] + S;
    }
}

// -- K3: enc = tanh(h@W2'+b2'), single-term A; MMA distances + softmax ------
__global__ __launch_bounds__(256, 3)
void k_gemm2(const float* __restrict__ att) {
    extern __shared__ unsigned sm[];
    // A double buffer: buf b at b*2304, [64][36] each
    unsigned* Bs  = sm + 4608;     // [128][36]
    unsigned* atH = sm + 9216;     // [16][68]
    unsigned* atL = sm + 10304;    // [16][68]
    float* b2ps = (float*)(sm + 11392);  // [128]
    float* asqS = (float*)(sm + 11520);  // [16]
    float* dotS = (float*)(sm + 11536);  // [64][20]
    float* esqP = (float*)(sm + 12816);  // [4][64]; total 13072 words
    // phase-2 aliases (A bufs + Bs dead)
    unsigned* eH = sm;             // [64][68]
    unsigned* eL = sm + 4352;      // [64][68] ends 8704
    const int t = threadIdx.x, w = t >> 5, lane = t & 31;
    const int gid = lane >> 2, q = lane & 3;
    const int wm = w >> 2, wn = w & 3, rowb = wm * 32, colb = wn * 32;
    const size_t row0 = (size_t)blockIdx.x * 64;
    const unsigned* w2w = (const unsigned*)g_w2f;

    for (int i = t; i < 1088; i += 256) {
        int n = i / 68, pw = i - n * 68;
        float v0 = 0.f, v1 = 0.f;
        if (n < 10 && pw < 64) { v0 = att[n * 128 + 2 * pw]; v1 = att[n * 128 + 2 * pw + 1]; }
        unsigned hp, lp;
        packpairh(v0, v1, hp, lp);
        atH[i] = hp; atL[i] = lp;
    }
    if (t < 128) b2ps[t] = g_b2p[t];
    if (t >= 128 && t < 144) {
        int k = t - 128;
        float a2 = 0.f;
        if (k < 10)
            for (int c = 0; c < 128; c++) { float x = att[k * 128 + c]; a2 += x * x; }
        asqS[k] = a2;
    }

    float acc[2][4][4];
#pragma unroll
    for (int m = 0; m < 2; m++)
#pragma unroll
        for (int na = 0; na < 4; na++)
#pragma unroll
            for (int j = 0; j < 4; j++) acc[m][na][j] = 0.f;

    for (int i = t; i < 512; i += 256) {
        int r = i >> 3, c8 = i & 7;
        cpa16(sm + r * 36 + c8 * 4, g_hh + (row0 + r) * 128 + c8 * 4);
    }
    CPCOMMIT;
    for (int kc = 0; kc < 4; kc++) {
        if (kc < 3) {
            unsigned* dst = sm + ((kc + 1) & 1) * 2304;
            for (int i = t; i < 512; i += 256) {
                int r = i >> 3, c8 = i & 7;
                cpa16(dst + r * 36 + c8 * 4, g_hh + (row0 + r) * 128 + (kc + 1) * 32 + c8 * 4);
            }
            CPCOMMIT;
        }
        for (int i = t; i < 1024; i += 256) {
            int n = i >> 3, c8 = i & 7;
            *(uint4*)(Bs + n * 36 + c8 * 4) = *(const uint4*)(w2w + (size_t)n * 128 + kc * 32 + c8 * 4);
        }
        if (kc < 3) { CPWAIT1; } else { CPWAIT0; }
        __syncthreads();
        unsigned* As = sm + (kc & 1) * 2304;
#pragma unroll
        for (int ks = 0; ks < 4; ks++) {
            unsigned ah[2][4];
#pragma unroll
            for (int m = 0; m < 2; m++) {
                int b = (rowb + 16 * m + gid) * 36 + ks * 8 + q;
                ah[m][0] = As[b]; ah[m][1] = As[b + 288]; ah[m][2] = As[b + 4]; ah[m][3] = As[b + 292];
            }
#pragma unroll
            for (int na = 0; na < 4; na++) {
                int bb = (colb + 8 * na + gid) * 36 + ks * 8 + q;
                unsigned bh[2] = {Bs[bb], Bs[bb + 4]};
#pragma unroll
                for (int m = 0; m < 2; m++) mma16h(acc[m][na], ah[m], bh);
            }
        }
        __syncthreads();
    }
    // tanh epilogue: enc -> eH/eL smem + gmem hi; ||e||^2 partials
    float p2[4] = {0.f, 0.f, 0.f, 0.f};
#pragma unroll
    for (int na = 0; na < 4; na++) {
        int cl = colb + 8 * na + 2 * q, pw = (cl >> 1);
        float bb0 = b2ps[cl], bb1 = b2ps[cl + 1];
#pragma unroll
        for (int m = 0; m < 2; m++) {
            int r = rowb + 16 * m + gid;
            float e00 = tanhf(acc[m][na][0] + bb0), e01 = tanhf(acc[m][na][1] + bb1);
            float e10 = tanhf(acc[m][na][2] + bb0), e11 = tanhf(acc[m][na][3] + bb1);
            unsigned hp, lp;
            packpairh(e00, e01, hp, lp);
            eH[r * 68 + pw] = hp; eL[r * 68 + pw] = lp;
            g_ench[(row0 + r) * 64 + pw] = hp;
            packpairh(e10, e11, hp, lp);
            eH[(r + 8) * 68 + pw] = hp; eL[(r + 8) * 68 + pw] = lp;
            g_ench[(row0 + r + 8) * 64 + pw] = hp;
            p2[2 * m]     += e00 * e00 + e01 * e01;
            p2[2 * m + 1] += e10 * e10 + e11 * e11;
        }
    }
#pragma unroll
    for (int j = 0; j < 4; j++) {
        p2[j] += __shfl_xor_sync(0xffffffffu, p2[j], 1);
        p2[j] += __shfl_xor_sync(0xffffffffu, p2[j], 2);
    }
    if (q == 0) {
#pragma unroll
        for (int m = 0; m < 2; m++) {
            esqP[wn * 64 + rowb + 16 * m + gid]     = p2[2 * m];
            esqP[wn * 64 + rowb + 16 * m + gid + 8] = p2[2 * m + 1];
        }
    }
    __syncthreads();
    // dot = enc . att^T via 3-term fp16 MMA
    {
        const int mt = w >> 1, nt = w & 1;
        float d4[4] = {0.f, 0.f, 0.f, 0.f};
#pragma unroll
        for (int term = 0; term < 3; term++) {
            const unsigned* Aop = (term == 1) ? eL : eH;
            const unsigned* Bop = (term == 2) ? atL : atH;
#pragma unroll
            for (int ks = 0; ks < 8; ks++) {
                int b = (mt * 16 + gid) * 68 + ks * 8 + q;
                unsigned a[4] = {Aop[b], Aop[b + 544], Aop[b + 4], Aop[b + 548]};
                int bb = (nt * 8 + gid) * 68 + ks * 8 + q;
                unsigned bh[2] = {Bop[bb], Bop[bb + 4]};
                mma16h(d4, a, bh);
            }
        }
        int r = mt * 16 + gid, cc = nt * 8 + 2 * q;
        dotS[r * 20 + cc] = d4[0];       dotS[r * 20 + cc + 1] = d4[1];
        dotS[(r + 8) * 20 + cc] = d4[2]; dotS[(r + 8) * 20 + cc + 1] = d4[3];
    }
    __syncthreads();
    if (t < 64) {
        float esqv = esqP[t] + esqP[64 + t] + esqP[128 + t] + esqP[192 + t];
        float d[10];
#pragma unroll
        for (int k = 0; k < 10; k++)
            d[k] = sqrtf(fmaxf(esqv - 2.f * dotS[t * 20 + k] + asqS[k], 0.f));
        float dmin = d[0];
#pragma unroll
        for (int k = 1; k < 10; k++) dmin = fminf(dmin, d[k]);
        float s[10], Z = 0.f;
#pragma unroll
        for (int k = 0; k < 10; k++) { s[k] = expf(-2.f * (d[k] - dmin)); Z += s[k]; }
        float invZ = 1.f / Z;
#pragma unroll
        for (int k = 0; k < 10; k++) g_s[(row0 + t) * 10 + k] = s[k] * invZ;
    }
}

// ------------- K4: fused experts (fp16 k16) + gated contraction ------------
__global__ __launch_bounds__(512, 2)
void k_fused(const float* __restrict__ be1, const float* __restrict__ be2,
             float* __restrict__ out) {
    extern __shared__ unsigned sm[];
    unsigned* Ae  = sm;                  // enc fp16 [128][68]
    unsigned* buf = sm + 8704;           // We1 [128][68] / eh [128][68]
    unsigned* B2  = sm + 17408;          // [16][68]
    float* sS   = (float*)(sm + 18496);  // [128][12]
    float* sBe  = (float*)(sm + 20032);  // [128]
    float* be2S = (float*)(sm + 20160);  // [100 used]; total 20288 words
    const int t = threadIdx.x, w = t >> 5, lane = t & 31;
    const int gid = lane >> 2, q = lane & 3;
    const int wm = w >> 2, wn = w & 3;
    const size_t row0 = (size_t)blockIdx.x * 128;

    for (int i = t; i < 2048; i += 512) {
        int r = i >> 4, c4 = i & 15;
        cpa16(Ae + r * 68 + c4 * 4, g_ench + (row0 + r) * 64 + c4 * 4);
    }
    CPCOMMIT;
    for (int i = t; i < 1280; i += 512) {
        int r = i / 10, k = i - r * 10;
        sS[r * 12 + k] = g_s[(row0 + r) * 10 + k];
    }
    if (t < 100) be2S[t] = be2[t];

    float acc2[2][4];
#pragma unroll
    for (int nf = 0; nf < 2; nf++)
#pragma unroll
        for (int j = 0; j < 4; j++) acc2[nf][j] = 0.f;

    for (int g = 0; g < 5; g++) {
        __syncthreads();
        for (int i = t; i < 2048; i += 512) {
            int j = i >> 4, c4 = i & 15;
            cpa16(buf + j * 68 + c4 * 4, g_we1p + g * 8192 + j * 64 + c4 * 4);
        }
        CPCOMMIT;
        if (t < 128) sBe[t] = be1[g * 128 + t];
        for (int i = t; i < 272; i += 512)
            ((uint4*)B2)[i] = ((const uint4*)(g_w2c + g * 1088))[i];
        CPWAIT0;
        __syncthreads();

        float acc[2][4][4];
#pragma unroll
        for (int m = 0; m < 2; m++)
#pragma unroll
            for (int na = 0; na < 4; na++)
#pragma unroll
                for (int j = 0; j < 4; j++) acc[m][na][j] = 0.f;
#pragma unroll
        for (int ks = 0; ks < 8; ks++) {
            unsigned a[2][4];
#pragma unroll
            for (int m = 0; m < 2; m++) {
                int b = (wm * 32 + 16 * m + gid) * 68 + ks * 8 + q;
                a[m][0] = Ae[b]; a[m][1] = Ae[b + 544]; a[m][2] = Ae[b + 4]; a[m][3] = Ae[b + 548];
            }
#pragma unroll
            for (int na = 0; na < 4; na++) {
                int bb = (wn * 32 + 8 * na + gid) * 68 + ks * 8 + q;
                unsigned bh[2] = {buf[bb], buf[bb + 4]};
                mma16h(acc[0][na], a[0], bh);
                mma16h(acc[1][na], a[1], bh);
            }
        }
        __syncthreads();
#pragma unroll
        for (int na = 0; na < 4; na++) {
            int jc = wn * 32 + 8 * na + 2 * q, pw = wn * 16 + 4 * na + q;
            float bia0 = sBe[jc], bia1 = sBe[jc + 1];
            int k0 = 2 * g + (jc >> 6);
#pragma unroll
            for (int m = 0; m < 2; m++) {
                int rr = wm * 32 + 16 * m + gid;
                float s0 = sS[rr * 12 + k0], s1 = sS[(rr + 8) * 12 + k0];
                buf[rr * 68 + pw] = packh(fmaxf(acc[m][na][0] + bia0, 0.f) * s0,
                                          fmaxf(acc[m][na][1] + bia1, 0.f) * s0);
                buf[(rr + 8) * 68 + pw] = packh(fmaxf(acc[m][na][2] + bia0, 0.f) * s1,
                                                fmaxf(acc[m][na][3] + bia1, 0.f) * s1);
            }
        }
        __syncthreads();
        if (w < 8) {
#pragma unroll
            for (int ks = 0; ks < 8; ks++) {
                int b = (w * 16 + gid) * 68 + ks * 8 + q;
                unsigned a2[4] = {buf[b], buf[b + 544], buf[b + 4], buf[b + 548]};
#pragma unroll
                for (int nf = 0; nf < 2; nf++) {
                    int bb = (nf * 8 + gid) * 68 + ks * 8 + q;
                    unsigned bh[2] = {B2[bb], B2[bb + 4]};
                    mma16h(acc2[nf], a2, bh);
                }
            }
        }
    }
    if (w < 8) {
        const int rl = w * 16 + gid;
        const size_t r = row0 + rl;
        float b0 = 0.f, b1 = 0.f, b2a = 0.f, b3 = 0.f;
        float c0 = 0.f, c1 = 0.f, c2 = 0.f, c3 = 0.f;
#pragma unroll
        for (int k = 0; k < 10; k++) {
            float s0 = sS[rl * 12 + k], s1 = sS[(rl + 8) * 12 + k];
            float w0 = be2S[k * 10 + 2 * q], w1 = be2S[k * 10 + 2 * q + 1];
            b0 += s0 * w0; b1 += s0 * w1; b2a += s1 * w0; b3 += s1 * w1;
            if (q == 0) {
                float w8 = be2S[k * 10 + 8], w9 = be2S[k * 10 + 9];
                c0 += s0 * w8; c1 += s0 * w9; c2 += s1 * w8; c3 += s1 * w9;
            }
        }
        out[r * 10 + 2 * q]           = acc2[0][0] + b0;
        out[r * 10 + 2 * q + 1]       = acc2[0][1] + b1;
        out[(r + 8) * 10 + 2 * q]     = acc2[0][2] + b2a;
        out[(r + 8) * 10 + 2 * q + 1] = acc2[0][3] + b3;
        if (q == 0) {
            out[r * 10 + 8] = acc2[1][0] + c0;       out[r * 10 + 9] = acc2[1][1] + c1;
            out[(r + 8) * 10 + 8] = acc2[1][2] + c2; out[(r + 8) * 10 + 9] = acc2[1][3] + c3;
        }
    }
}

// ---------------------------------------------------------------------------
extern "C" void kernel_launch(void* const* d_in, const int* in_sizes, int n_in,
                              void* d_out, int out_size) {
    const float* state = (const float*)d_in[0];
    const float* W1    = (const float*)d_in[1];
    const float* b1    = (const float*)d_in[2];
    const float* gamma = (const float*)d_in[3];
    const float* beta  = (const float*)d_in[4];
    const float* W2    = (const float*)d_in[5];
    const float* b2    = (const float*)d_in[6];
    const float* We1   = (const float*)d_in[7];
    const float* be1   = (const float*)d_in[8];
    const float* We2   = (const float*)d_in[9];
    const float* be2   = (const float*)d_in[10];
    const float* att   = (const float*)d_in[11];
    float* out = (float*)d_out;

    const int SM1 = 6912 * 4, SM2 = 13072 * 4, SMF = 20288 * 4;
    cudaFuncSetAttribute(k_gemm1, cudaFuncAttributeMaxDynamicSharedMemorySize, SM1);
    cudaFuncSetAttribute(k_gemm2, cudaFuncAttributeMaxDynamicSharedMemorySize, SM2);
    cudaFuncSetAttribute(k_fused, cudaFuncAttributeMaxDynamicSharedMemorySize, SMF);

    k_prep <<<256, 256>>>(W1, We1, We2);
    k_gemm1<<<dim3(NB1, 2), 256, SM1>>>(state, b1);
    k_stats<<<256, 256>>>(gamma, beta);
    k_fold <<<128, 256>>>(W2, b2);
    k_gemm2<<<NB1, 256, SM2>>>(att);
    k_fused<<<NBF, 512, SMF>>>(be1, be2, out);
}

// round 13
// speedup vs baseline: 2.0144x; 1.0064x over previous
#include <cuda_runtime.h>
#include <cuda_fp16.h>
#include <math.h>

#define BTOT 262144
#define NB1  4096   // 64-row blocks

__device__ unsigned g_hh[(size_t)BTOT * 128];   // h fp16 pairs
__device__ float    g_psum[256 * NB1];
__device__ float    g_psq [256 * NB1];
__device__ float    g_A[256], g_Bb[256], g_b2p[128];
__device__ unsigned g_w1p[256 * 64];            // W1 fp16 pairs [n][pw]
__device__ unsigned short g_w2f[128 * 256];     // W2' fp16 [n][k]
__device__ unsigned g_we1p[5 * 128 * 64];       // We1 fp16 pairs
__device__ unsigned g_w2c [5 * 16 * 68];        // We2 fp16 pairs [g][a][j-pw]

__device__ __forceinline__ void mma16h(float* c, const unsigned* a, const unsigned* b) {
    asm volatile("mma.sync.aligned.m16n8k16.row.col.f32.f16.f16.f32 "
        "{%0,%1,%2,%3},{%4,%5,%6,%7},{%8,%9},{%0,%1,%2,%3};"
        : "+f"(c[0]), "+f"(c[1]), "+f"(c[2]), "+f"(c[3])
        : "r"(a[0]), "r"(a[1]), "r"(a[2]), "r"(a[3]), "r"(b[0]), "r"(b[1]));
}
__device__ __forceinline__ unsigned packh(float a, float b) {
    __half2 h = __floats2half2_rn(a, b); return *(unsigned*)&h;
}
__device__ __forceinline__ void packpairh(float v0, float v1, unsigned& hp, unsigned& lp) {
    __half h0 = __float2half_rn(v0), h1 = __float2half_rn(v1);
    hp = (unsigned)*(unsigned short*)&h0 | ((unsigned)*(unsigned short*)&h1 << 16);
    lp = packh(v0 - __half2float(h0), v1 - __half2float(h1));
}
__device__ __forceinline__ void cpa16(void* dst, const void* src) {
    unsigned d = (unsigned)__cvta_generic_to_shared(dst);
    asm volatile("cp.async.cg.shared.global [%0],[%1],16;\n" :: "r"(d), "l"(src));
}
#define CPCOMMIT asm volatile("cp.async.commit_group;\n")
#define CPWAIT0  asm volatile("cp.async.wait_group 0;\n")
#define CPWAIT1  asm volatile("cp.async.wait_group 1;\n")

// ------------------- prep -------------------
__global__ void k_prep(const float* __restrict__ W1, const float* __restrict__ We1,
                       const float* __restrict__ We2) {
    int idx = blockIdx.x * blockDim.x + threadIdx.x, st = gridDim.x * blockDim.x;
    for (int i = idx; i < 256 * 64; i += st) {
        int n = i >> 6, pw = i & 63;
        int k0 = 2 * pw, k1 = 2 * pw + 1;
        float v0 = (k0 < 100) ? W1[k0 * 256 + n] : 0.f;
        float v1 = (k1 < 100) ? W1[k1 * 256 + n] : 0.f;
        g_w1p[i] = packh(v0, v1);
    }
    for (int i = idx; i < 5 * 128 * 64; i += st) {
        int g = i >> 13, r = i & 8191, j = r >> 6, ep = r & 63;
        int sub = j >> 6, jl = j & 63;
        float v0 = We1[((size_t)(2 * g + sub) * 128 + 2 * ep) * 64 + jl];
        float v1 = We1[((size_t)(2 * g + sub) * 128 + 2 * ep + 1) * 64 + jl];
        g_we1p[i] = packh(v0, v1);
    }
    for (int i = idx; i < 5 * 16 * 68; i += st) {
        int g = i / 1088, r = i - g * 1088, a = r / 68, pw = r - a * 68;
        float v0 = 0.f, v1 = 0.f;
        if (a < 10 && pw < 64) {
            int j0 = 2 * pw, j1 = 2 * pw + 1;
            v0 = We2[(size_t)((2 * g + (j0 >> 6)) * 64 + (j0 & 63)) * 10 + a];
            v1 = We2[(size_t)((2 * g + (j1 >> 6)) * 64 + (j1 & 63)) * 10 + a];
        }
        g_w2c[i] = packh(v0, v1);
    }
}

// -- K1: h = relu(state@W1+b1). single fp16, K=112. -----------------
__global__ __launch_bounds__(256, 3)
void k_gemm1(const float* __restrict__ state, const float* __restrict__ b1) {
    extern __shared__ unsigned sm[];
    unsigned* As = sm;             // [64][36]
    unsigned* Bs = sm + 2304;      // [128][36]; end 6912 words
    const int t = threadIdx.x, w = t >> 5, lane = t & 31;
    const int gid = lane >> 2, q = lane & 3;
    const int wm = w >> 2, wn = w & 3, rowb = wm * 32, colb = wn * 32;
    const int rb = blockIdx.x, cb = blockIdx.y;
    const size_t row0 = (size_t)rb * 64;

    float acc[2][4][4];
#pragma unroll
    for (int m = 0; m < 2; m++)
#pragma unroll
        for (int na = 0; na < 4; na++)
#pragma unroll
            for (int j = 0; j < 4; j++) acc[m][na][j] = 0.f;

    for (int kc = 0; kc < 2; kc++) {
        __syncthreads();
        {
            int r = t >> 2, sl = t & 3, c0 = kc * 64 + sl * 16;
            float vv[16];
#pragma unroll
            for (int u = 0; u < 4; u++) {
                int k = c0 + u * 4;
                float4 x = (k < 100) ? *(const float4*)(state + (row0 + r) * 100 + k)
                                     : make_float4(0.f, 0.f, 0.f, 0.f);
                vv[4 * u] = x.x; vv[4 * u + 1] = x.y; vv[4 * u + 2] = x.z; vv[4 * u + 3] = x.w;
            }
            unsigned H[8];
#pragma unroll
            for (int u = 0; u < 8; u++) H[u] = packh(vv[2 * u], vv[2 * u + 1]);
            *(uint4*)(As + r * 36 + sl * 8)     = make_uint4(H[0], H[1], H[2], H[3]);
            *(uint4*)(As + r * 36 + sl * 8 + 4) = make_uint4(H[4], H[5], H[6], H[7]);
        }
        for (int i = t; i < 1024; i += 256) {
            int n = i >> 3, c8 = i & 7;
            *(uint4*)(Bs + n * 36 + c8 * 4) =
                *(const uint4*)(g_w1p + (size_t)(cb * 128 + n) * 64 + kc * 32 + c8 * 4);
        }
        __syncthreads();
        const int kcnt = kc ? 3 : 4;
        for (int ks = 0; ks < kcnt; ks++) {
            unsigned ah[2][4];
#pragma unroll
            for (int m = 0; m < 2; m++) {
                int b = (rowb + 16 * m + gid) * 36 + ks * 8 + q;
                ah[m][0] = As[b]; ah[m][1] = As[b + 288]; ah[m][2] = As[b + 4]; ah[m][3] = As[b + 292];
            }
#pragma unroll
            for (int na = 0; na < 4; na++) {
                int bb = (colb + 8 * na + gid) * 36 + ks * 8 + q;
                unsigned bh[2] = {Bs[bb], Bs[bb + 4]};
#pragma unroll
                for (int m = 0; m < 2; m++) mma16h(acc[m][na], ah[m], bh);
            }
        }
    }
    __syncthreads();
    float* sums = (float*)sm;
    float* sqs  = sums + 256;
#pragma unroll
    for (int na = 0; na < 4; na++) {
        int cg = colb + 8 * na + 2 * q, cgg = cb * 128 + cg;
        float bias0 = b1[cgg], bias1 = b1[cgg + 1];
        float p0 = 0.f, p1 = 0.f, q0 = 0.f, q1 = 0.f;
#pragma unroll
        for (int m = 0; m < 2; m++) {
            size_t r = row0 + rowb + 16 * m + gid;
            float v00 = fmaxf(acc[m][na][0] + bias0, 0.f), v01 = fmaxf(acc[m][na][1] + bias1, 0.f);
            float v10 = fmaxf(acc[m][na][2] + bias0, 0.f), v11 = fmaxf(acc[m][na][3] + bias1, 0.f);
            g_hh[r * 128 + (cgg >> 1)]       = packh(v00, v01);
            g_hh[(r + 8) * 128 + (cgg >> 1)] = packh(v10, v11);
            p0 += v00 + v10; p1 += v01 + v11;
            q0 += v00 * v00 + v10 * v10; q1 += v01 * v01 + v11 * v11;
        }
#pragma unroll
        for (int off = 4; off <= 16; off <<= 1) {
            p0 += __shfl_xor_sync(0xffffffffu, p0, off);
            p1 += __shfl_xor_sync(0xffffffffu, p1, off);
            q0 += __shfl_xor_sync(0xffffffffu, q0, off);
            q1 += __shfl_xor_sync(0xffffffffu, q1, off);
        }
        if (gid == 0) {
            sums[wm * 128 + cg] = p0; sums[wm * 128 + cg + 1] = p1;
            sqs [wm * 128 + cg] = q0; sqs [wm * 128 + cg + 1] = q1;
        }
    }
    __syncthreads();
    if (t < 128) {
        g_psum[(cb * 128 + t) * NB1 + rb] = sums[t] + sums[128 + t];
        g_psq [(cb * 128 + t) * NB1 + rb] = sqs[t] + sqs[128 + t];
    }
}

// ------------------- K2: BN stats finalize -------------------
__global__ __launch_bounds__(256)
void k_stats(const float* __restrict__ gamma, const float* __restrict__ beta) {
    const int c = blockIdx.x, t = threadIdx.x;
    float s = 0.f, qq = 0.f;
    for (int i = t; i < NB1; i += 256) { s += g_psum[c * NB1 + i]; qq += g_psq[c * NB1 + i]; }
#pragma unroll
    for (int off = 16; off; off >>= 1) {
        s += __shfl_xor_sync(0xffffffffu, s, off);
        qq += __shfl_xor_sync(0xffffffffu, qq, off);
    }
    __shared__ float ss[8], sq[8];
    if ((t & 31) == 0) { ss[t >> 5] = s; sq[t >> 5] = qq; }
    __syncthreads();
    if (t == 0) {
        float S = 0.f, Q = 0.f;
#pragma unroll
        for (int wv = 0; wv < 8; wv++) { S += ss[wv]; Q += sq[wv]; }
        const float inv_n = 1.f / (float)BTOT;
        float mu = S * inv_n;
        float var = Q * inv_n - mu * mu;
        float rstd = rsqrtf(var + 1e-5f);
        float gg = gamma[c];
        g_A[c] = rstd * gg;
        g_Bb[c] = beta[c] - mu * rstd * gg;
    }
}

// ------------- K2b: fold BN into W2 (fp16) + b2' ---------------
__global__ __launch_bounds__(256)
void k_fold(const float* __restrict__ W2, const float* __restrict__ b2) {
    const int n = blockIdx.x, k = threadIdx.x;
    float wv = W2[k * 128 + n];
    __half hf = __float2half_rn(g_A[k] * wv);
    g_w2f[n * 256 + k] = *(unsigned short*)&hf;
    float p = g_Bb[k] * wv;
#pragma unroll
    for (int off = 16; off; off >>= 1) p += __shfl_xor_sync(0xffffffffu, p, off);
    __shared__ float red[8];
    if ((k & 31) == 0) red[k >> 5] = p;
    __syncthreads();
    if (k == 0) {
        float S = 0.f;
#pragma unroll
        for (int i = 0; i < 8; i++) S += red[i];
        g_b2p[n] = b2[n] + S;
    }
}

// -- K3: fully fused tail: enc GEMM + tanh + distances + softmax + experts --
// 64 rows per block, 256 threads, 60.7 KB smem (3 blocks/SM).
__global__ __launch_bounds__(256, 3)
void k_tail(const float* __restrict__ att, const float* __restrict__ be1,
            const float* __restrict__ be2, float* __restrict__ out) {
    extern __shared__ unsigned sm[];
    // phase A: A-dbuf at 0 / 2304 ([64][36] each)
    unsigned* Bs  = sm + 4608;           // [128][36]
    unsigned* atH = sm + 9216;           // [16][68]
    unsigned* atL = sm + 10304;
    float* b2ps = (float*)(sm + 11392);  // [128]
    float* asqS = (float*)(sm + 11520);  // [16]
    float* dotS = (float*)(sm + 11536);  // [64][20]
    float* esqP = (float*)(sm + 12816);  // [4][64] ends 13072
    // persistent tail region
    float* sS   = (float*)(sm + 13072);  // [64][12]
    float* sBe  = (float*)(sm + 13840);  // [128]
    float* be2S = (float*)(sm + 13968);  // [112]
    unsigned* B2 = sm + 14080;           // [16][68]; total 15168 words
    // phase B/C aliases
    unsigned* eH   = sm;                 // [64][68]
    unsigned* eL   = sm + 4352;          // [64][68] (dead after distance)
    unsigned* wbuf = sm + 4352;          // [128][68] We1 -> eh (4352..13056)
    const int t = threadIdx.x, w = t >> 5, lane = t & 31;
    const int gid = lane >> 2, q = lane & 3;
    const int wm = w >> 2, wn = w & 3, rowb = wm * 32, colb = wn * 32;
    const size_t row0 = (size_t)blockIdx.x * 64;
    const unsigned* w2w = (const unsigned*)g_w2f;

    for (int i = t; i < 1088; i += 256) {
        int n = i / 68, pw = i - n * 68;
        float v0 = 0.f, v1 = 0.f;
        if (n < 10 && pw < 64) { v0 = att[n * 128 + 2 * pw]; v1 = att[n * 128 + 2 * pw + 1]; }
        unsigned hp, lp;
        packpairh(v0, v1, hp, lp);
        atH[i] = hp; atL[i] = lp;
    }
    if (t < 128) b2ps[t] = g_b2p[t];
    if (t >= 128 && t < 144) {
        int k = t - 128;
        float a2 = 0.f;
        if (k < 10)
            for (int c = 0; c < 128; c++) { float x = att[k * 128 + c]; a2 += x * x; }
        asqS[k] = a2;
    }
    if (t >= 144 && t < 244) be2S[t - 144] = be2[t - 144];

    float acc[2][4][4];
#pragma unroll
    for (int m = 0; m < 2; m++)
#pragma unroll
        for (int na = 0; na < 4; na++)
#pragma unroll
            for (int j = 0; j < 4; j++) acc[m][na][j] = 0.f;

    // ---- phase A: enc main GEMM (h @ W2'), A double-buffered ----
    for (int i = t; i < 512; i += 256) {
        int r = i >> 3, c8 = i & 7;
        cpa16(sm + r * 36 + c8 * 4, g_hh + (row0 + r) * 128 + c8 * 4);
    }
    CPCOMMIT;
    for (int kc = 0; kc < 4; kc++) {
        if (kc < 3) {
            unsigned* dst = sm + ((kc + 1) & 1) * 2304;
            for (int i = t; i < 512; i += 256) {
                int r = i >> 3, c8 = i & 7;
                cpa16(dst + r * 36 + c8 * 4, g_hh + (row0 + r) * 128 + (kc + 1) * 32 + c8 * 4);
            }
            CPCOMMIT;
        }
        for (int i = t; i < 1024; i += 256) {
            int n = i >> 3, c8 = i & 7;
            *(uint4*)(Bs + n * 36 + c8 * 4) = *(const uint4*)(w2w + (size_t)n * 128 + kc * 32 + c8 * 4);
        }
        if (kc < 3) { CPWAIT1; } else { CPWAIT0; }
        __syncthreads();
        unsigned* As = sm + (kc & 1) * 2304;
#pragma unroll
        for (int ks = 0; ks < 4; ks++) {
            unsigned ah[2][4];
#pragma unroll
            for (int m = 0; m < 2; m++) {
                int b = (rowb + 16 * m + gid) * 36 + ks * 8 + q;
                ah[m][0] = As[b]; ah[m][1] = As[b + 288]; ah[m][2] = As[b + 4]; ah[m][3] = As[b + 292];
            }
#pragma unroll
            for (int na = 0; na < 4; na++) {
                int bb = (colb + 8 * na + gid) * 36 + ks * 8 + q;
                unsigned bh[2] = {Bs[bb], Bs[bb + 4]};
#pragma unroll
                for (int m = 0; m < 2; m++) mma16h(acc[m][na], ah[m], bh);
            }
        }
        __syncthreads();
    }
    // ---- tanh epilogue: enc -> eH/eL; ||e||^2 partials ----
    float p2[4] = {0.f, 0.f, 0.f, 0.f};
#pragma unroll
    for (int na = 0; na < 4; na++) {
        int cl = colb + 8 * na + 2 * q, pw = (cl >> 1);
        float bb0 = b2ps[cl], bb1 = b2ps[cl + 1];
#pragma unroll
        for (int m = 0; m < 2; m++) {
            int r = rowb + 16 * m + gid;
            float e00 = tanhf(acc[m][na][0] + bb0), e01 = tanhf(acc[m][na][1] + bb1);
            float e10 = tanhf(acc[m][na][2] + bb0), e11 = tanhf(acc[m][na][3] + bb1);
            unsigned hp, lp;
            packpairh(e00, e01, hp, lp);
            eH[r * 68 + pw] = hp; eL[r * 68 + pw] = lp;
            packpairh(e10, e11, hp, lp);
            eH[(r + 8) * 68 + pw] = hp; eL[(r + 8) * 68 + pw] = lp;
            p2[2 * m]     += e00 * e00 + e01 * e01;
            p2[2 * m + 1] += e10 * e10 + e11 * e11;
        }
    }
#pragma unroll
    for (int j = 0; j < 4; j++) {
        p2[j] += __shfl_xor_sync(0xffffffffu, p2[j], 1);
        p2[j] += __shfl_xor_sync(0xffffffffu, p2[j], 2);
    }
    if (q == 0) {
#pragma unroll
        for (int m = 0; m < 2; m++) {
            esqP[wn * 64 + rowb + 16 * m + gid]     = p2[2 * m];
            esqP[wn * 64 + rowb + 16 * m + gid + 8] = p2[2 * m + 1];
        }
    }
    __syncthreads();
    // ---- distance dot = enc . att^T (3-term fp16 MMA) ----
    {
        const int mt = w >> 1, nt = w & 1;
        float d4[4] = {0.f, 0.f, 0.f, 0.f};
#pragma unroll
        for (int term = 0; term < 3; term++) {
            const unsigned* Aop = (term == 1) ? eL : eH;
            const unsigned* Bop = (term == 2) ? atL : atH;
#pragma unroll
            for (int ks = 0; ks < 8; ks++) {
                int b = (mt * 16 + gid) * 68 + ks * 8 + q;
                unsigned a[4] = {Aop[b], Aop[b + 544], Aop[b + 4], Aop[b + 548]};
                int bb = (nt * 8 + gid) * 68 + ks * 8 + q;
                unsigned bh[2] = {Bop[bb], Bop[bb + 4]};
                mma16h(d4, a, bh);
            }
        }
        int r = mt * 16 + gid, cc = nt * 8 + 2 * q;
        dotS[r * 20 + cc] = d4[0];       dotS[r * 20 + cc + 1] = d4[1];
        dotS[(r + 8) * 20 + cc] = d4[2]; dotS[(r + 8) * 20 + cc + 1] = d4[3];
    }
    __syncthreads();
    // ---- softmax -> sS (smem) ----
    if (t < 64) {
        float esqv = esqP[t] + esqP[64 + t] + esqP[128 + t] + esqP[192 + t];
        float d[10];
#pragma unroll
        for (int k = 0; k < 10; k++)
            d[k] = sqrtf(fmaxf(esqv - 2.f * dotS[t * 20 + k] + asqS[k], 0.f));
        float dmin = d[0];
#pragma unroll
        for (int k = 1; k < 10; k++) dmin = fminf(dmin, d[k]);
        float s[10], Z = 0.f;
#pragma unroll
        for (int k = 0; k < 10; k++) { s[k] = expf(-2.f * (d[k] - dmin)); Z += s[k]; }
        float invZ = 1.f / Z;
#pragma unroll
        for (int k = 0; k < 10; k++) sS[t * 12 + k] = s[k] * invZ;
    }

    // ---- expert phase: per group mma1 -> eh -> mma2 ----
    float acc2[2][4];
#pragma unroll
    for (int nf = 0; nf < 2; nf++)
#pragma unroll
        for (int j = 0; j < 4; j++) acc2[nf][j] = 0.f;

    for (int g = 0; g < 5; g++) {
        __syncthreads();
        for (int i = t; i < 2048; i += 256) {
            int j = i >> 4, c4 = i & 15;
            cpa16(wbuf + j * 68 + c4 * 4, g_we1p + g * 8192 + j * 64 + c4 * 4);
        }
        CPCOMMIT;
        if (t < 128) sBe[t] = be1[g * 128 + t];
        for (int i = t; i < 272; i += 256)
            ((uint4*)B2)[i] = ((const uint4*)(g_w2c + g * 1088))[i];
        CPWAIT0;
        __syncthreads();

        float acce[2][4][4];
#pragma unroll
        for (int m = 0; m < 2; m++)
#pragma unroll
            for (int na = 0; na < 4; na++)
#pragma unroll
                for (int j = 0; j < 4; j++) acce[m][na][j] = 0.f;
#pragma unroll
        for (int ks = 0; ks < 8; ks++) {
            unsigned a[2][4];
#pragma unroll
            for (int m = 0; m < 2; m++) {
                int b = (rowb + 16 * m + gid) * 68 + ks * 8 + q;
                a[m][0] = eH[b]; a[m][1] = eH[b + 544]; a[m][2] = eH[b + 4]; a[m][3] = eH[b + 548];
            }
#pragma unroll
            for (int na = 0; na < 4; na++) {
                int bb = (colb + 8 * na + gid) * 68 + ks * 8 + q;
                unsigned bh[2] = {wbuf[bb], wbuf[bb + 4]};
                mma16h(acce[0][na], a[0], bh);
                mma16h(acce[1][na], a[1], bh);
            }
        }
        __syncthreads();
        // eh = relu(acce+be1)*s -> wbuf rows 0..63 (fp16 pairs)
#pragma unroll
        for (int na = 0; na < 4; na++) {
            int jc = colb + 8 * na + 2 * q, pw = wn * 16 + 4 * na + q;
            float bia0 = sBe[jc], bia1 = sBe[jc + 1];
            int k0 = 2 * g + (jc >> 6);
#pragma unroll
            for (int m = 0; m < 2; m++) {
                int rr = rowb + 16 * m + gid;
                float s0 = sS[rr * 12 + k0], s1 = sS[(rr + 8) * 12 + k0];
                wbuf[rr * 68 + pw] = packh(fmaxf(acce[m][na][0] + bia0, 0.f) * s0,
                                           fmaxf(acce[m][na][1] + bia1, 0.f) * s0);
                wbuf[(rr + 8) * 68 + pw] = packh(fmaxf(acce[m][na][2] + bia0, 0.f) * s1,
                                                 fmaxf(acce[m][na][3] + bia1, 0.f) * s1);
            }
        }
        __syncthreads();
        if (w < 4) {
#pragma unroll
            for (int ks = 0; ks < 8; ks++) {
                int b = (w * 16 + gid) * 68 + ks * 8 + q;
                unsigned a2[4] = {wbuf[b], wbuf[b + 544], wbuf[b + 4], wbuf[b + 548]};
#pragma unroll
                for (int nf = 0; nf < 2; nf++) {
                    int bb = (nf * 8 + gid) * 68 + ks * 8 + q;
                    unsigned bh[2] = {B2[bb], B2[bb + 4]};
                    mma16h(acc2[nf], a2, bh);
                }
            }
        }
    }
    if (w < 4) {
        const int rl = w * 16 + gid;
        const size_t r = row0 + rl;
        float b0 = 0.f, b1 = 0.f, b2a = 0.f, b3 = 0.f;
        float c0 = 0.f, c1 = 0.f, c2 = 0.f, c3 = 0.f;
#pragma unroll
        for (int k = 0; k < 10; k++) {
            float s0 = sS[rl * 12 + k], s1 = sS[(rl + 8) * 12 + k];
            float w0 = be2S[k * 10 + 2 * q], w1 = be2S[k * 10 + 2 * q + 1];
            b0 += s0 * w0; b1 += s0 * w1; b2a += s1 * w0; b3 += s1 * w1;
            if (q == 0) {
                float w8 = be2S[k * 10 + 8], w9 = be2S[k * 10 + 9];
                c0 += s0 * w8; c1 += s0 * w9; c2 += s1 * w8; c3 += s1 * w9;
            }
        }
        out[r * 10 + 2 * q]           = acc2[0][0] + b0;
        out[r * 10 + 2 * q + 1]       = acc2[0][1] + b1;
        out[(r + 8) * 10 + 2 * q]     = acc2[0][2] + b2a;
        out[(r + 8) * 10 + 2 * q + 1] = acc2[0][3] + b3;
        if (q == 0) {
            out[r * 10 + 8] = acc2[1][0] + c0;       out[r * 10 + 9] = acc2[1][1] + c1;
            out[(r + 8) * 10 + 8] = acc2[1][2] + c2; out[(r + 8) * 10 + 9] = acc2[1][3] + c3;
        }
    }
}

// ---------------------------------------------------------------------------
extern "C" void kernel_launch(void* const* d_in, const int* in_sizes, int n_in,
                              void* d_out, int out_size) {
    const float* state = (const float*)d_in[0];
    const float* W1    = (const float*)d_in[1];
    const float* b1    = (const float*)d_in[2];
    const float* gamma = (const float*)d_in[3];
    const float* beta  = (const float*)d_in[4];
    const float* W2    = (const float*)d_in[5];
    const float* b2    = (const float*)d_in[6];
    const float* We1   = (const float*)d_in[7];
    const float* be1   = (const float*)d_in[8];
    const float* We2   = (const float*)d_in[9];
    const float* be2   = (const float*)d_in[10];
    const float* att   = (const float*)d_in[11];
    float* out = (float*)d_out;

    const int SM1 = 6912 * 4, SMT = 15168 * 4;
    cudaFuncSetAttribute(k_gemm1, cudaFuncAttributeMaxDynamicSharedMemorySize, SM1);
    cudaFuncSetAttribute(k_tail,  cudaFuncAttributeMaxDynamicSharedMemorySize, SMT);

    k_prep <<<256, 256>>>(W1, We1, We2);
    k_gemm1<<<dim3(NB1, 2), 256, SM1>>>(state, b1);
    k_stats<<<256, 256>>>(gamma, beta);
    k_fold <<<128, 256>>>(W2, b2);
    k_tail <<<NB1, 256, SMT>>>(att, be1, be2, out);
}

// round 14
// speedup vs baseline: 2.1471x; 1.0659x over previous
#include <cuda_runtime.h>
#include <cuda_fp16.h>
#include <math.h>

#define BTOT 262144
#define NB1  4096   // gemm1 64-row blocks
#define NBT  2048   // tail 128-row blocks

__device__ unsigned g_hh[(size_t)BTOT * 128];   // h fp16 pairs
__device__ float    g_psum[256 * NB1];
__device__ float    g_psq [256 * NB1];
__device__ float    g_A[256], g_Bb[256], g_b2p[128];
__device__ unsigned g_w1p[256 * 64];            // W1 fp16 pairs [n][pw]
__device__ unsigned short g_w2f[128 * 256];     // W2' fp16 [n][k]
__device__ unsigned g_we1p[5 * 128 * 64];       // We1 fp16 pairs
__device__ unsigned g_w2c [5 * 16 * 68];        // We2 fp16 pairs [g][a][j-pw]

__device__ __forceinline__ void mma16h(float* c, const unsigned* a, const unsigned* b) {
    asm volatile("mma.sync.aligned.m16n8k16.row.col.f32.f16.f16.f32 "
        "{%0,%1,%2,%3},{%4,%5,%6,%7},{%8,%9},{%0,%1,%2,%3};"
        : "+f"(c[0]), "+f"(c[1]), "+f"(c[2]), "+f"(c[3])
        : "r"(a[0]), "r"(a[1]), "r"(a[2]), "r"(a[3]), "r"(b[0]), "r"(b[1]));
}
__device__ __forceinline__ unsigned packh(float a, float b) {
    __half2 h = __floats2half2_rn(a, b); return *(unsigned*)&h;
}
__device__ __forceinline__ void packpairh(float v0, float v1, unsigned& hp, unsigned& lp) {
    __half h0 = __float2half_rn(v0), h1 = __float2half_rn(v1);
    hp = (unsigned)*(unsigned short*)&h0 | ((unsigned)*(unsigned short*)&h1 << 16);
    lp = packh(v0 - __half2float(h0), v1 - __half2float(h1));
}
__device__ __forceinline__ void cpa16(void* dst, const void* src) {
    unsigned d = (unsigned)__cvta_generic_to_shared(dst);
    asm volatile("cp.async.cg.shared.global [%0],[%1],16;\n" :: "r"(d), "l"(src));
}
#define CPCOMMIT asm volatile("cp.async.commit_group;\n")
#define CPWAIT0  asm volatile("cp.async.wait_group 0;\n")
#define CPWAIT1  asm volatile("cp.async.wait_group 1;\n")

// ------------------- prep -------------------
__global__ void k_prep(const float* __restrict__ W1, const float* __restrict__ We1,
                       const float* __restrict__ We2) {
    int idx = blockIdx.x * blockDim.x + threadIdx.x, st = gridDim.x * blockDim.x;
    for (int i = idx; i < 256 * 64; i += st) {
        int n = i >> 6, pw = i & 63;
        int k0 = 2 * pw, k1 = 2 * pw + 1;
        float v0 = (k0 < 100) ? W1[k0 * 256 + n] : 0.f;
        float v1 = (k1 < 100) ? W1[k1 * 256 + n] : 0.f;
        g_w1p[i] = packh(v0, v1);
    }
    for (int i = idx; i < 5 * 128 * 64; i += st) {
        int g = i >> 13, r = i & 8191, j = r >> 6, ep = r & 63;
        int sub = j >> 6, jl = j & 63;
        float v0 = We1[((size_t)(2 * g + sub) * 128 + 2 * ep) * 64 + jl];
        float v1 = We1[((size_t)(2 * g + sub) * 128 + 2 * ep + 1) * 64 + jl];
        g_we1p[i] = packh(v0, v1);
    }
    for (int i = idx; i < 5 * 16 * 68; i += st) {
        int g = i / 1088, r = i - g * 1088, a = r / 68, pw = r - a * 68;
        float v0 = 0.f, v1 = 0.f;
        if (a < 10 && pw < 64) {
            int j0 = 2 * pw, j1 = 2 * pw + 1;
            v0 = We2[(size_t)((2 * g + (j0 >> 6)) * 64 + (j0 & 63)) * 10 + a];
            v1 = We2[(size_t)((2 * g + (j1 >> 6)) * 64 + (j1 & 63)) * 10 + a];
        }
        g_w2c[i] = packh(v0, v1);
    }
}

// -- K1: h = relu(state@W1+b1). single fp16, K=112. -----------------
__global__ __launch_bounds__(256, 3)
void k_gemm1(const float* __restrict__ state, const float* __restrict__ b1) {
    extern __shared__ unsigned sm[];
    unsigned* As = sm;             // [64][36]
    unsigned* Bs = sm + 2304;      // [128][36]; end 6912 words
    const int t = threadIdx.x, w = t >> 5, lane = t & 31;
    const int gid = lane >> 2, q = lane & 3;
    const int wm = w >> 2, wn = w & 3, rowb = wm * 32, colb = wn * 32;
    const int rb = blockIdx.x, cb = blockIdx.y;
    const size_t row0 = (size_t)rb * 64;

    float acc[2][4][4];
#pragma unroll
    for (int m = 0; m < 2; m++)
#pragma unroll
        for (int na = 0; na < 4; na++)
#pragma unroll
            for (int j = 0; j < 4; j++) acc[m][na][j] = 0.f;

    for (int kc = 0; kc < 2; kc++) {
        __syncthreads();
        {
            int r = t >> 2, sl = t & 3, c0 = kc * 64 + sl * 16;
            float vv[16];
#pragma unroll
            for (int u = 0; u < 4; u++) {
                int k = c0 + u * 4;
                float4 x = (k < 100) ? *(const float4*)(state + (row0 + r) * 100 + k)
                                     : make_float4(0.f, 0.f, 0.f, 0.f);
                vv[4 * u] = x.x; vv[4 * u + 1] = x.y; vv[4 * u + 2] = x.z; vv[4 * u + 3] = x.w;
            }
            unsigned H[8];
#pragma unroll
            for (int u = 0; u < 8; u++) H[u] = packh(vv[2 * u], vv[2 * u + 1]);
            *(uint4*)(As + r * 36 + sl * 8)     = make_uint4(H[0], H[1], H[2], H[3]);
            *(uint4*)(As + r * 36 + sl * 8 + 4) = make_uint4(H[4], H[5], H[6], H[7]);
        }
        for (int i = t; i < 1024; i += 256) {
            int n = i >> 3, c8 = i & 7;
            *(uint4*)(Bs + n * 36 + c8 * 4) =
                *(const uint4*)(g_w1p + (size_t)(cb * 128 + n) * 64 + kc * 32 + c8 * 4);
        }
        __syncthreads();
        const int kcnt = kc ? 3 : 4;
        for (int ks = 0; ks < kcnt; ks++) {
            unsigned ah[2][4];
#pragma unroll
            for (int m = 0; m < 2; m++) {
                int b = (rowb + 16 * m + gid) * 36 + ks * 8 + q;
                ah[m][0] = As[b]; ah[m][1] = As[b + 288]; ah[m][2] = As[b + 4]; ah[m][3] = As[b + 292];
            }
#pragma unroll
            for (int na = 0; na < 4; na++) {
                int bb = (colb + 8 * na + gid) * 36 + ks * 8 + q;
                unsigned bh[2] = {Bs[bb], Bs[bb + 4]};
#pragma unroll
                for (int m = 0; m < 2; m++) mma16h(acc[m][na], ah[m], bh);
            }
        }
    }
    __syncthreads();
    float* sums = (float*)sm;
    float* sqs  = sums + 256;
#pragma unroll
    for (int na = 0; na < 4; na++) {
        int cg = colb + 8 * na + 2 * q, cgg = cb * 128 + cg;
        float bias0 = b1[cgg], bias1 = b1[cgg + 1];
        float p0 = 0.f, p1 = 0.f, q0 = 0.f, q1 = 0.f;
#pragma unroll
        for (int m = 0; m < 2; m++) {
            size_t r = row0 + rowb + 16 * m + gid;
            float v00 = fmaxf(acc[m][na][0] + bias0, 0.f), v01 = fmaxf(acc[m][na][1] + bias1, 0.f);
            float v10 = fmaxf(acc[m][na][2] + bias0, 0.f), v11 = fmaxf(acc[m][na][3] + bias1, 0.f);
            g_hh[r * 128 + (cgg >> 1)]       = packh(v00, v01);
            g_hh[(r + 8) * 128 + (cgg >> 1)] = packh(v10, v11);
            p0 += v00 + v10; p1 += v01 + v11;
            q0 += v00 * v00 + v10 * v10; q1 += v01 * v01 + v11 * v11;
        }
#pragma unroll
        for (int off = 4; off <= 16; off <<= 1) {
            p0 += __shfl_xor_sync(0xffffffffu, p0, off);
            p1 += __shfl_xor_sync(0xffffffffu, p1, off);
            q0 += __shfl_xor_sync(0xffffffffu, q0, off);
            q1 += __shfl_xor_sync(0xffffffffu, q1, off);
        }
        if (gid == 0) {
            sums[wm * 128 + cg] = p0; sums[wm * 128 + cg + 1] = p1;
            sqs [wm * 128 + cg] = q0; sqs [wm * 128 + cg + 1] = q1;
        }
    }
    __syncthreads();
    if (t < 128) {
        g_psum[(cb * 128 + t) * NB1 + rb] = sums[t] + sums[128 + t];
        g_psq [(cb * 128 + t) * NB1 + rb] = sqs[t] + sqs[128 + t];
    }
}

// ------------------- K2: BN stats finalize -------------------
__global__ __launch_bounds__(256)
void k_stats(const float* __restrict__ gamma, const float* __restrict__ beta) {
    const int c = blockIdx.x, t = threadIdx.x;
    float s = 0.f, qq = 0.f;
    for (int i = t; i < NB1; i += 256) { s += g_psum[c * NB1 + i]; qq += g_psq[c * NB1 + i]; }
#pragma unroll
    for (int off = 16; off; off >>= 1) {
        s += __shfl_xor_sync(0xffffffffu, s, off);
        qq += __shfl_xor_sync(0xffffffffu, qq, off);
    }
    __shared__ float ss[8], sq[8];
    if ((t & 31) == 0) { ss[t >> 5] = s; sq[t >> 5] = qq; }
    __syncthreads();
    if (t == 0) {
        float S = 0.f, Q = 0.f;
#pragma unroll
        for (int wv = 0; wv < 8; wv++) { S += ss[wv]; Q += sq[wv]; }
        const float inv_n = 1.f / (float)BTOT;
        float mu = S * inv_n;
        float var = Q * inv_n - mu * mu;
        float rstd = rsqrtf(var + 1e-5f);
        float gg = gamma[c];
        g_A[c] = rstd * gg;
        g_Bb[c] = beta[c] - mu * rstd * gg;
    }
}

// ------------- K2b: fold BN into W2 (fp16) + b2' ---------------
__global__ __launch_bounds__(256)
void k_fold(const float* __restrict__ W2, const float* __restrict__ b2) {
    const int n = blockIdx.x, k = threadIdx.x;
    float wv = W2[k * 128 + n];
    __half hf = __float2half_rn(g_A[k] * wv);
    g_w2f[n * 256 + k] = *(unsigned short*)&hf;
    float p = g_Bb[k] * wv;
#pragma unroll
    for (int off = 16; off; off >>= 1) p += __shfl_xor_sync(0xffffffffu, p, off);
    __shared__ float red[8];
    if ((k & 31) == 0) red[k >> 5] = p;
    __syncthreads();
    if (k == 0) {
        float S = 0.f;
#pragma unroll
        for (int i = 0; i < 8; i++) S += red[i];
        g_b2p[n] = b2[n] + S;
    }
}

// -- K3: fused tail (128 rows, 512 thr): enc GEMM + dist + softmax + experts
__global__ __launch_bounds__(512, 2)
void k_tail(const float* __restrict__ att, const float* __restrict__ be1,
            const float* __restrict__ be2, float* __restrict__ out) {
    extern __shared__ unsigned sm[];
    // phase A: A-dbuf at 0/4608 ([128][36] each); Bs at 9216 [128][36] -> 13824
    unsigned* Bs  = sm + 9216;
    // phase B/C aliases
    unsigned* eH   = sm;                 // [128][68] = 8704
    unsigned* eL   = sm + 8704;          // [128][68] (dead after distance)
    unsigned* wbuf = sm + 8704;          // [128][68] We1 -> eh
    // scratch (disjoint from all above)
    unsigned* atH = sm + 17408;          // [16][68]
    unsigned* atL = sm + 18496;
    float* b2ps = (float*)(sm + 19584);  // [128]
    float* asqS = (float*)(sm + 19712);  // [16]
    float* dotS = (float*)(sm + 19728);  // [128][20]
    float* esqP = (float*)(sm + 22288);  // [4][128]
    // persistent tail region
    float* sS   = (float*)(sm + 22800);  // [128][12]
    float* sBe  = (float*)(sm + 24336);  // [128]
    float* be2S = (float*)(sm + 24464);  // [112]
    unsigned* B2 = sm + 24576;           // [16][68]; total 25664 words
    const int t = threadIdx.x, w = t >> 5, lane = t & 31;
    const int gid = lane >> 2, q = lane & 3;
    const int wm = w >> 2, wn = w & 3, rowb = wm * 32, colb = wn * 32;
    const size_t row0 = (size_t)blockIdx.x * 128;
    const unsigned* w2w = (const unsigned*)g_w2f;

    for (int i = t; i < 1088; i += 512) {
        int n = i / 68, pw = i - n * 68;
        float v0 = 0.f, v1 = 0.f;
        if (n < 10 && pw < 64) { v0 = att[n * 128 + 2 * pw]; v1 = att[n * 128 + 2 * pw + 1]; }
        unsigned hp, lp;
        packpairh(v0, v1, hp, lp);
        atH[i] = hp; atL[i] = lp;
    }
    if (t < 128) b2ps[t] = g_b2p[t];
    if (t >= 128 && t < 144) {
        int k = t - 128;
        float a2 = 0.f;
        if (k < 10)
            for (int c = 0; c < 128; c++) { float x = att[k * 128 + c]; a2 += x * x; }
        asqS[k] = a2;
    }
    if (t >= 144 && t < 244) be2S[t - 144] = be2[t - 144];

    float acc[2][4][4];
#pragma unroll
    for (int m = 0; m < 2; m++)
#pragma unroll
        for (int na = 0; na < 4; na++)
#pragma unroll
            for (int j = 0; j < 4; j++) acc[m][na][j] = 0.f;

    // ---- phase A: enc main GEMM (h @ W2'), A double-buffered ----
    for (int i = t; i < 1024; i += 512) {
        int r = i >> 3, c8 = i & 7;
        cpa16(sm + r * 36 + c8 * 4, g_hh + (row0 + r) * 128 + c8 * 4);
    }
    CPCOMMIT;
    for (int kc = 0; kc < 4; kc++) {
        if (kc < 3) {
            unsigned* dst = sm + ((kc + 1) & 1) * 4608;
            for (int i = t; i < 1024; i += 512) {
                int r = i >> 3, c8 = i & 7;
                cpa16(dst + r * 36 + c8 * 4, g_hh + (row0 + r) * 128 + (kc + 1) * 32 + c8 * 4);
            }
            CPCOMMIT;
        }
        for (int i = t; i < 1024; i += 512) {
            int n = i >> 3, c8 = i & 7;
            *(uint4*)(Bs + n * 36 + c8 * 4) = *(const uint4*)(w2w + (size_t)n * 128 + kc * 32 + c8 * 4);
        }
        if (kc < 3) { CPWAIT1; } else { CPWAIT0; }
        __syncthreads();
        unsigned* As = sm + (kc & 1) * 4608;
#pragma unroll
        for (int ks = 0; ks < 4; ks++) {
            unsigned ah[2][4];
#pragma unroll
            for (int m = 0; m < 2; m++) {
                int b = (rowb + 16 * m + gid) * 36 + ks * 8 + q;
                ah[m][0] = As[b]; ah[m][1] = As[b + 288]; ah[m][2] = As[b + 4]; ah[m][3] = As[b + 292];
            }
#pragma unroll
            for (int na = 0; na < 4; na++) {
                int bb = (colb + 8 * na + gid) * 36 + ks * 8 + q;
                unsigned bh[2] = {Bs[bb], Bs[bb + 4]};
#pragma unroll
                for (int m = 0; m < 2; m++) mma16h(acc[m][na], ah[m], bh);
            }
        }
        __syncthreads();
    }
    // ---- tanh epilogue: enc -> eH/eL; ||e||^2 partials ----
    float p2[4] = {0.f, 0.f, 0.f, 0.f};
#pragma unroll
    for (int na = 0; na < 4; na++) {
        int cl = colb + 8 * na + 2 * q, pw = (cl >> 1);
        float bb0 = b2ps[cl], bb1 = b2ps[cl + 1];
#pragma unroll
        for (int m = 0; m < 2; m++) {
            int r = rowb + 16 * m + gid;
            float e00 = tanhf(acc[m][na][0] + bb0), e01 = tanhf(acc[m][na][1] + bb1);
            float e10 = tanhf(acc[m][na][2] + bb0), e11 = tanhf(acc[m][na][3] + bb1);
            unsigned hp, lp;
            packpairh(e00, e01, hp, lp);
            eH[r * 68 + pw] = hp; eL[r * 68 + pw] = lp;
            packpairh(e10, e11, hp, lp);
            eH[(r + 8) * 68 + pw] = hp; eL[(r + 8) * 68 + pw] = lp;
            p2[2 * m]     += e00 * e00 + e01 * e01;
            p2[2 * m + 1] += e10 * e10 + e11 * e11;
        }
    }
#pragma unroll
    for (int j = 0; j < 4; j++) {
        p2[j] += __shfl_xor_sync(0xffffffffu, p2[j], 1);
        p2[j] += __shfl_xor_sync(0xffffffffu, p2[j], 2);
    }
    if (q == 0) {
#pragma unroll
        for (int m = 0; m < 2; m++) {
            esqP[wn * 128 + rowb + 16 * m + gid]     = p2[2 * m];
            esqP[wn * 128 + rowb + 16 * m + gid + 8] = p2[2 * m + 1];
        }
    }
    __syncthreads();
    // ---- distance dot = enc . att^T (3-term fp16 MMA), 16 warps ----
    {
        const int mt = w >> 1, nt = w & 1;
        float d4[4] = {0.f, 0.f, 0.f, 0.f};
#pragma unroll
        for (int term = 0; term < 3; term++) {
            const unsigned* Aop = (term == 1) ? eL : eH;
            const unsigned* Bop = (term == 2) ? atL : atH;
#pragma unroll
            for (int ks = 0; ks < 8; ks++) {
                int b = (mt * 16 + gid) * 68 + ks * 8 + q;
                unsigned a[4] = {Aop[b], Aop[b + 544], Aop[b + 4], Aop[b + 548]};
                int bb = (nt * 8 + gid) * 68 + ks * 8 + q;
                unsigned bh[2] = {Bop[bb], Bop[bb + 4]};
                mma16h(d4, a, bh);
            }
        }
        int r = mt * 16 + gid, cc = nt * 8 + 2 * q;
        dotS[r * 20 + cc] = d4[0];       dotS[r * 20 + cc + 1] = d4[1];
        dotS[(r + 8) * 20 + cc] = d4[2]; dotS[(r + 8) * 20 + cc + 1] = d4[3];
    }
    __syncthreads();
    // ---- softmax -> sS ----
    if (t < 128) {
        float esqv = esqP[t] + esqP[128 + t] + esqP[256 + t] + esqP[384 + t];
        float d[10];
#pragma unroll
        for (int k = 0; k < 10; k++)
            d[k] = sqrtf(fmaxf(esqv - 2.f * dotS[t * 20 + k] + asqS[k], 0.f));
        float dmin = d[0];
#pragma unroll
        for (int k = 1; k < 10; k++) dmin = fminf(dmin, d[k]);
        float s[10], Z = 0.f;
#pragma unroll
        for (int k = 0; k < 10; k++) { s[k] = expf(-2.f * (d[k] - dmin)); Z += s[k]; }
        float invZ = 1.f / Z;
#pragma unroll
        for (int k = 0; k < 10; k++) sS[t * 12 + k] = s[k] * invZ;
    }

    // ---- expert phase (eL dead; wbuf aliases it) ----
    float acc2[2][4];
#pragma unroll
    for (int nf = 0; nf < 2; nf++)
#pragma unroll
        for (int j = 0; j < 4; j++) acc2[nf][j] = 0.f;

    for (int g = 0; g < 5; g++) {
        __syncthreads();
        for (int i = t; i < 2048; i += 512) {
            int j = i >> 4, c4 = i & 15;
            cpa16(wbuf + j * 68 + c4 * 4, g_we1p + g * 8192 + j * 64 + c4 * 4);
        }
        CPCOMMIT;
        if (t < 128) sBe[t] = be1[g * 128 + t];
        for (int i = t; i < 272; i += 512)
            ((uint4*)B2)[i] = ((const uint4*)(g_w2c + g * 1088))[i];
        CPWAIT0;
        __syncthreads();

        float acce[2][4][4];
#pragma unroll
        for (int m = 0; m < 2; m++)
#pragma unroll
            for (int na = 0; na < 4; na++)
#pragma unroll
                for (int j = 0; j < 4; j++) acce[m][na][j] = 0.f;
#pragma unroll
        for (int ks = 0; ks < 8; ks++) {
            unsigned a[2][4];
#pragma unroll
            for (int m = 0; m < 2; m++) {
                int b = (rowb + 16 * m + gid) * 68 + ks * 8 + q;
                a[m][0] = eH[b]; a[m][1] = eH[b + 544]; a[m][2] = eH[b + 4]; a[m][3] = eH[b + 548];
            }
#pragma unroll
            for (int na = 0; na < 4; na++) {
                int bb = (colb + 8 * na + gid) * 68 + ks * 8 + q;
                unsigned bh[2] = {wbuf[bb], wbuf[bb + 4]};
                mma16h(acce[0][na], a[0], bh);
                mma16h(acce[1][na], a[1], bh);
            }
        }
        __syncthreads();
#pragma unroll
        for (int na = 0; na < 4; na++) {
            int jc = colb + 8 * na + 2 * q, pw = wn * 16 + 4 * na + q;
            float bia0 = sBe[jc], bia1 = sBe[jc + 1];
            int k0 = 2 * g + (jc >> 6);
#pragma unroll
            for (int m = 0; m < 2; m++) {
                int rr = rowb + 16 * m + gid;
                float s0 = sS[rr * 12 + k0], s1 = sS[(rr + 8) * 12 + k0];
                wbuf[rr * 68 + pw] = packh(fmaxf(acce[m][na][0] + bia0, 0.f) * s0,
                                           fmaxf(acce[m][na][1] + bia1, 0.f) * s0);
                wbuf[(rr + 8) * 68 + pw] = packh(fmaxf(acce[m][na][2] + bia0, 0.f) * s1,
                                                 fmaxf(acce[m][na][3] + bia1, 0.f) * s1);
            }
        }
        __syncthreads();
        if (w < 8) {
#pragma unroll
            for (int ks = 0; ks < 8; ks++) {
                int b = (w * 16 + gid) * 68 + ks * 8 + q;
                unsigned a2[4] = {wbuf[b], wbuf[b + 544], wbuf[b + 4], wbuf[b + 548]};
#pragma unroll
                for (int nf = 0; nf < 2; nf++) {
                    int bb = (nf * 8 + gid) * 68 + ks * 8 + q;
                    unsigned bh[2] = {B2[bb], B2[bb + 4]};
                    mma16h(acc2[nf], a2, bh);
                }
            }
        }
    }
    if (w < 8) {
        const int rl = w * 16 + gid;
        const size_t r = row0 + rl;
        float b0 = 0.f, b1 = 0.f, b2a = 0.f, b3 = 0.f;
        float c0 = 0.f, c1 = 0.f, c2 = 0.f, c3 = 0.f;
#pragma unroll
        for (int k = 0; k < 10; k++) {
            float s0 = sS[rl * 12 + k], s1 = sS[(rl + 8) * 12 + k];
            float w0 = be2S[k * 10 + 2 * q], w1 = be2S[k * 10 + 2 * q + 1];
            b0 += s0 * w0; b1 += s0 * w1; b2a += s1 * w0; b3 += s1 * w1;
            if (q == 0) {
                float w8 = be2S[k * 10 + 8], w9 = be2S[k * 10 + 9];
                c0 += s0 * w8; c1 += s0 * w9; c2 += s1 * w8; c3 += s1 * w9;
            }
        }
        out[r * 10 + 2 * q]           = acc2[0][0] + b0;
        out[r * 10 + 2 * q + 1]       = acc2[0][1] + b1;
        out[(r + 8) * 10 + 2 * q]     = acc2[0][2] + b2a;
        out[(r + 8) * 10 + 2 * q + 1] = acc2[0][3] + b3;
        if (q == 0) {
            out[r * 10 + 8] = acc2[1][0] + c0;       out[r * 10 + 9] = acc2[1][1] + c1;
            out[(r + 8) * 10 + 8] = acc2[1][2] + c2; out[(r + 8) * 10 + 9] = acc2[1][3] + c3;
        }
    }
}

// ---------------------------------------------------------------------------
extern "C" void kernel_launch(void* const* d_in, const int* in_sizes, int n_in,
                              void* d_out, int out_size) {
    const float* state = (const float*)d_in[0];
    const float* W1    = (const float*)d_in[1];
    const float* b1    = (const float*)d_in[2];
    const float* gamma = (const float*)d_in[3];
    const float* beta  = (const float*)d_in[4];
    const float* W2    = (const float*)d_in[5];
    const float* b2    = (const float*)d_in[6];
    const float* We1   = (const float*)d_in[7];
    const float* be1   = (const float*)d_in[8];
    const float* We2   = (const float*)d_in[9];
    const float* be2   = (const float*)d_in[10];
    const float* att   = (const float*)d_in[11];
    float* out = (float*)d_out;

    const int SM1 = 6912 * 4, SMT = 25664 * 4;
    cudaFuncSetAttribute(k_gemm1, cudaFuncAttributeMaxDynamicSharedMemorySize, SM1);
    cudaFuncSetAttribute(k_tail,  cudaFuncAttributeMaxDynamicSharedMemorySize, SMT);

    k_prep <<<256, 256>>>(W1, We1, We2);
    k_gemm1<<<dim3(NB1, 2), 256, SM1>>>(state, b1);
    k_stats<<<256, 256>>>(gamma, beta);
    k_fold <<<128, 256>>>(W2, b2);
    k_tail <<<NBT, 512, SMT>>>(att, be1, be2, out);
}